// round 12
// baseline (speedup 1.0000x reference)
#include <cuda_runtime.h>
#include <math.h>

#define BB 64
#define TT 500
#define SS 50
#define DD 64
#define NTOK (BB*TT)
#define NCHUNK 10
#define CLEN 50
#define NBLK_SCAN (BB * 4 * NCHUNK)   // 2560

typedef unsigned long long u64;

__device__ float g_w[(size_t)NTOK*SS];
__device__ float g_e[(size_t)NTOK*DD];
__device__ float g_a[(size_t)NTOK*DD];
__device__ float g_r[(size_t)NTOK*DD];
// affine chunk maps + boundary states: [blk(2560)][tid(128)*4]
__device__ u64 gA2[(size_t)NBLK_SCAN*512];
__device__ u64 gB2[(size_t)NBLK_SCAN*512];
__device__ u64 g_mvb[(size_t)NBLK_SCAN*512];

__device__ __forceinline__ float fast_sigmoid(float x) {
    return 1.f / (1.f + __expf(-x));
}
__device__ __forceinline__ float fast_tanh(float x) {
    return fmaf(2.f, fast_sigmoid(2.f * x), -1.f);
}

// ---- packed f32x2 helpers ----
__device__ __forceinline__ u64 ffma2(u64 a, u64 b, u64 c) {
    u64 d;
    asm("fma.rn.f32x2 %0, %1, %2, %3;" : "=l"(d) : "l"(a), "l"(b), "l"(c));
    return d;
}
__device__ __forceinline__ u64 fmul2(u64 a, u64 b) {
    u64 d;
    asm("mul.rn.f32x2 %0, %1, %2;" : "=l"(d) : "l"(a), "l"(b));
    return d;
}
__device__ __forceinline__ u64 fadd2(u64 a, u64 b) {
    u64 d;
    asm("add.rn.f32x2 %0, %1, %2;" : "=l"(d) : "l"(a), "l"(b));
    return d;
}
__device__ __forceinline__ u64 splat2(float x) {
    u64 d;
    asm("mov.b64 %0, {%1, %1};" : "=l"(d) : "r"(__float_as_uint(x)));
    return d;
}
__device__ __forceinline__ u64 pack2(float lo, float hi) {
    u64 d;
    asm("mov.b64 %0, {%1, %2};" : "=l"(d) : "r"(__float_as_uint(lo)), "r"(__float_as_uint(hi)));
    return d;
}
__device__ __forceinline__ float2 unpack2(u64 v) {
    unsigned int lo, hi;
    asm("mov.b64 {%0, %1}, %2;" : "=r"(lo), "=r"(hi) : "l"(v));
    return make_float2(__uint_as_float(lo), __uint_as_float(hi));
}

extern __shared__ float dynsh[];

// ============================================================
// k_front: FUSED scores-softmax + e/a gates. Grid 250, 2 tiles.
// (unchanged from R11 best)
// ============================================================
#define SROW 52
__global__ __launch_bounds__(256) void k_front(const int* __restrict__ concept,
                                               const int* __restrict__ correct,
                                               const int* __restrict__ nc_ptr,
                                               const float* __restrict__ ek,
                                               const float* __restrict__ ev,
                                               const float* __restrict__ Mk,
                                               const float* __restrict__ We,
                                               const float* __restrict__ be,
                                               const float* __restrict__ Wa,
                                               const float* __restrict__ ba) {
    float* sMkT = dynsh;
    float* sWe  = dynsh + 3376;
    float* sWa  = dynsh + 7472;
    float* sxk  = dynsh + 11568;
    float* sxv  = dynsh + 15664;
    __shared__ int sc_[64], sidx[64];

    int tid = threadIdx.x;
    int td = tid & 15, tt = tid >> 4;
    int nc = *nc_ptr;

    for (int q = tid; q < 3376; q += 256) sMkT[q] = 0.f;
    __syncthreads();
    for (int q = tid; q < SS * DD; q += 256) {
        int s = q >> 6, k = q & 63;
        sMkT[k * SROW + s] = Mk[q];
    }
    {
        float4* sWe4w = (float4*)sWe;
        float4* sWa4w = (float4*)sWa;
        const float4* We4 = (const float4*)We;
        const float4* Wa4 = (const float4*)Wa;
        for (int q = tid; q < 1024; q += 256) {
            sWe4w[q] = We4[q];
            sWa4w[q] = Wa4[q];
        }
    }
    float4 bev = *(const float4*)(be + 4 * td);
    float4 bav = *(const float4*)(ba + 4 * td);

    for (int tile = 0; tile < 2; ++tile) {
        int base = (blockIdx.x * 2 + tile) * 64;

        __syncthreads();
        if (tid < 64) {
            int c = concept[base + tid];
            sc_[tid] = c;
            sidx[tid] = c + nc * correct[base + tid];
        }
        __syncthreads();
        {
            float4* sxk4 = (float4*)sxk;
            float4* sxv4 = (float4*)sxv;
            const float4* ek4 = (const float4*)ek;
            const float4* ev4 = (const float4*)ev;
            for (int q = tid; q < 1024; q += 256) {
                int tok = q >> 4, kk = q & 15;
                sxk4[q] = ek4[(size_t)sc_[tok] * 16 + kk];
                sxv4[q] = ev4[(size_t)sidx[tok] * 16 + kk];
            }
        }
        __syncthreads();

        {
            const float4* sM4 = (const float4*)sMkT;
            const float4* sx4 = (const float4*)sxk;
            u64 acc[4][2];
#pragma unroll
            for (int j = 0; j < 4; ++j) { acc[j][0] = 0ull; acc[j][1] = 0ull; }

#pragma unroll
            for (int kk = 0; kk < 16; ++kk) {
                ulonglong2 w0 = *(const ulonglong2*)(sM4 + (4 * kk + 0) * 13 + td);
                ulonglong2 w1 = *(const ulonglong2*)(sM4 + (4 * kk + 1) * 13 + td);
                ulonglong2 w2 = *(const ulonglong2*)(sM4 + (4 * kk + 2) * 13 + td);
                ulonglong2 w3 = *(const ulonglong2*)(sM4 + (4 * kk + 3) * 13 + td);
#pragma unroll
                for (int j = 0; j < 4; ++j) {
                    float4 xv = sx4[(tt + 16 * j) * 16 + kk];
                    u64 x0 = splat2(xv.x), x1 = splat2(xv.y), x2 = splat2(xv.z), x3 = splat2(xv.w);
                    acc[j][0] = ffma2(x0, w0.x, acc[j][0]);
                    acc[j][1] = ffma2(x0, w0.y, acc[j][1]);
                    acc[j][0] = ffma2(x1, w1.x, acc[j][0]);
                    acc[j][1] = ffma2(x1, w1.y, acc[j][1]);
                    acc[j][0] = ffma2(x2, w2.x, acc[j][0]);
                    acc[j][1] = ffma2(x2, w2.y, acc[j][1]);
                    acc[j][0] = ffma2(x3, w3.x, acc[j][0]);
                    acc[j][1] = ffma2(x3, w3.y, acc[j][1]);
                }
            }

#pragma unroll
            for (int j = 0; j < 4; ++j) {
                float2 a01 = unpack2(acc[j][0]);
                float2 a23 = unpack2(acc[j][1]);
                float e0 = (4 * td + 0) < SS ? __expf(a01.x) : 0.f;
                float e1 = (4 * td + 1) < SS ? __expf(a01.y) : 0.f;
                float e2 = (4 * td + 2) < SS ? __expf(a23.x) : 0.f;
                float e3 = (4 * td + 3) < SS ? __expf(a23.y) : 0.f;
                float p = e0 + e1 + e2 + e3;
                p += __shfl_xor_sync(0xffffffffu, p, 1);
                p += __shfl_xor_sync(0xffffffffu, p, 2);
                p += __shfl_xor_sync(0xffffffffu, p, 4);
                p += __shfl_xor_sync(0xffffffffu, p, 8);
                float inv = 1.f / p;
                int tok = base + tt + 16 * j;
                float* gwp = g_w + (size_t)tok * SS + 4 * td;
                if (td < 12) {
                    *(float2*)gwp       = make_float2(e0 * inv, e1 * inv);
                    *(float2*)(gwp + 2) = make_float2(e2 * inv, e3 * inv);
                } else if (td == 12) {
                    *(float2*)gwp       = make_float2(e0 * inv, e1 * inv);
                }
            }
        }

        {
            const float4* sWe4 = (const float4*)sWe;
            const float4* sWa4 = (const float4*)sWa;
            const float4* sx4 = (const float4*)sxv;
            u64 ae[4][2], aa[4][2];
#pragma unroll
            for (int j = 0; j < 4; ++j) {
                ae[j][0] = ae[j][1] = 0ull;
                aa[j][0] = aa[j][1] = 0ull;
            }

#pragma unroll
            for (int kk = 0; kk < 16; ++kk) {
                ulonglong2 e0 = *(const ulonglong2*)(sWe4 + (4 * kk + 0) * 16 + td);
                ulonglong2 e1 = *(const ulonglong2*)(sWe4 + (4 * kk + 1) * 16 + td);
                ulonglong2 e2 = *(const ulonglong2*)(sWe4 + (4 * kk + 2) * 16 + td);
                ulonglong2 e3 = *(const ulonglong2*)(sWe4 + (4 * kk + 3) * 16 + td);
                ulonglong2 a0 = *(const ulonglong2*)(sWa4 + (4 * kk + 0) * 16 + td);
                ulonglong2 a1 = *(const ulonglong2*)(sWa4 + (4 * kk + 1) * 16 + td);
                ulonglong2 a2 = *(const ulonglong2*)(sWa4 + (4 * kk + 2) * 16 + td);
                ulonglong2 a3 = *(const ulonglong2*)(sWa4 + (4 * kk + 3) * 16 + td);
#pragma unroll
                for (int j = 0; j < 4; ++j) {
                    float4 xv = sx4[(tt + 16 * j) * 16 + kk];
                    u64 x0 = splat2(xv.x), x1 = splat2(xv.y), x2 = splat2(xv.z), x3 = splat2(xv.w);
                    ae[j][0] = ffma2(x0, e0.x, ae[j][0]);
                    ae[j][1] = ffma2(x0, e0.y, ae[j][1]);
                    aa[j][0] = ffma2(x0, a0.x, aa[j][0]);
                    aa[j][1] = ffma2(x0, a0.y, aa[j][1]);
                    ae[j][0] = ffma2(x1, e1.x, ae[j][0]);
                    ae[j][1] = ffma2(x1, e1.y, ae[j][1]);
                    aa[j][0] = ffma2(x1, a1.x, aa[j][0]);
                    aa[j][1] = ffma2(x1, a1.y, aa[j][1]);
                    ae[j][0] = ffma2(x2, e2.x, ae[j][0]);
                    ae[j][1] = ffma2(x2, e2.y, ae[j][1]);
                    aa[j][0] = ffma2(x2, a2.x, aa[j][0]);
                    aa[j][1] = ffma2(x2, a2.y, aa[j][1]);
                    ae[j][0] = ffma2(x3, e3.x, ae[j][0]);
                    ae[j][1] = ffma2(x3, e3.y, ae[j][1]);
                    aa[j][0] = ffma2(x3, a3.x, aa[j][0]);
                    aa[j][1] = ffma2(x3, a3.y, aa[j][1]);
                }
            }

#pragma unroll
            for (int j = 0; j < 4; ++j) {
                size_t tok = (size_t)(base + tt + 16 * j);
                float2 ae01 = unpack2(ae[j][0]);
                float2 ae23 = unpack2(ae[j][1]);
                float2 aa01 = unpack2(aa[j][0]);
                float2 aa23 = unpack2(aa[j][1]);
                float4 eo, ao;
                eo.x = fast_sigmoid(ae01.x + bev.x);
                eo.y = fast_sigmoid(ae01.y + bev.y);
                eo.z = fast_sigmoid(ae23.x + bev.z);
                eo.w = fast_sigmoid(ae23.y + bev.w);
                ao.x = fast_tanh(aa01.x + bav.x);
                ao.y = fast_tanh(aa01.y + bav.y);
                ao.z = fast_tanh(aa23.x + bav.z);
                ao.w = fast_tanh(aa23.y + bav.w);
                *(float4*)(g_e + tok * DD + 4 * td) = eo;
                *(float4*)(g_a + tok * DD + 4 * td) = ao;
            }
        }
    }
}

// ============================================================
// Scan phase A: per (b, dq, chunk) block compute affine chunk map
// (A,B): Mv_end = A*Mv_start + B. 2560 blocks, 128 thr, no in-loop
// barriers. smem: sw [50][64] | se [50][16] | sa [50][16] = 4800 f.
// ============================================================
__global__ __launch_bounds__(128) void k_scanA() {
    float* sw = dynsh;            // 3200
    float* se = dynsh + 3200;     // 800
    float* sa = dynsh + 4000;     // 800

    int blk = blockIdx.x;
    int dq = blk & 3;
    int bc = blk >> 2;
    int c = bc % NCHUNK, b = bc / NCHUNK;
    int tid = threadIdx.x;
    int dl = tid >> 3, h = tid & 7;
    int sbase = h * 8;
    int t0 = c * CLEN;

    for (int q = tid; q < CLEN * 14; q += 128) {
        int t = q / 14, p = q % 14;
        sw[t * 64 + 50 + p] = 0.f;
    }

    const float* gw = g_w + ((size_t)b * TT + t0) * SS;
    const float* ge = g_e + ((size_t)b * TT + t0) * DD + dq * 16;
    const float* ga = g_a + ((size_t)b * TT + t0) * DD + dq * 16;

    for (int q = tid; q < CLEN * 25; q += 128) {
        int t = q / 25, p = q % 25;
        *(float2*)&sw[t * 64 + 2 * p] = *(const float2*)(gw + (size_t)t * SS + 2 * p);
    }
    for (int q = tid; q < CLEN * 4; q += 128) {
        int t = q >> 2, p = q & 3;
        *(float4*)&se[t * 16 + 4 * p] = *(const float4*)(ge + (size_t)t * DD + 4 * p);
        *(float4*)&sa[t * 16 + 4 * p] = *(const float4*)(ga + (size_t)t * DD + 4 * p);
    }
    __syncthreads();

    const u64 ONE2 = splat2(1.f);
    u64 A2[4] = {ONE2, ONE2, ONE2, ONE2};
    u64 B2[4] = {0ull, 0ull, 0ull, 0ull};

#pragma unroll 5
    for (int t = 0; t < CLEN; ++t) {
        float e_d = se[t * 16 + dl];
        float a_d = sa[t * 16 + dl];
        u64 ne2 = splat2(-e_d);
        u64 as2 = splat2(a_d);
        ulonglong2 wA = *(const ulonglong2*)&sw[t * 64 + sbase];
        ulonglong2 wB = *(const ulonglong2*)&sw[t * 64 + sbase + 4];
        u64 f0 = ffma2(wA.x, ne2, ONE2);
        u64 f1 = ffma2(wA.y, ne2, ONE2);
        u64 f2 = ffma2(wB.x, ne2, ONE2);
        u64 f3 = ffma2(wB.y, ne2, ONE2);
        A2[0] = fmul2(A2[0], f0);
        A2[1] = fmul2(A2[1], f1);
        A2[2] = fmul2(A2[2], f2);
        A2[3] = fmul2(A2[3], f3);
        B2[0] = ffma2(B2[0], f0, fmul2(wA.x, as2));
        B2[1] = ffma2(B2[1], f1, fmul2(wA.y, as2));
        B2[2] = ffma2(B2[2], f2, fmul2(wB.x, as2));
        B2[3] = ffma2(B2[3], f3, fmul2(wB.y, as2));
    }

    size_t o = (size_t)blk * 512 + tid * 4;
#pragma unroll
    for (int i = 0; i < 4; ++i) {
        gA2[o + i] = A2[i];
        gB2[o + i] = B2[i];
    }
}

// ============================================================
// Scan phase B: compose chunk maps -> boundary states g_mvb.
// Grid 256 = (b, dq), 128 thr; each thread owns 4 packed (s-pair, d).
// ============================================================
__global__ __launch_bounds__(128) void k_scanB(const float* __restrict__ Mv0) {
    int m = blockIdx.x;
    int dq = m & 3, b = m >> 2;
    int tid = threadIdx.x;
    int dl = tid >> 3, h = tid & 7;
    int d = dq * 16 + dl;
    int sbase = h * 8;

    u64 mv2[4];
#pragma unroll
    for (int i = 0; i < 4; ++i) {
        int s0 = sbase + 2 * i, s1 = s0 + 1;
        float lo = (s0 < SS) ? Mv0[s0 * DD + d] : 0.f;
        float hi = (s1 < SS) ? Mv0[s1 * DD + d] : 0.f;
        mv2[i] = pack2(lo, hi);
    }

    for (int c = 0; c < NCHUNK; ++c) {
        size_t o = (size_t)(((b * NCHUNK + c) * 4 + dq)) * 512 + tid * 4;
#pragma unroll
        for (int i = 0; i < 4; ++i) {
            g_mvb[o + i] = mv2[i];
            mv2[i] = ffma2(gA2[o + i], mv2[i], gB2[o + i]);
        }
    }
}

// ============================================================
// Scan phase C: replay each chunk from known boundary state, emit r.
// 2560 blocks, 128 thr. smem: sw 3200 | se 800 | sa 800 | srp 2560 = 7360 f.
// Shuffle-free reduction per 10-step sub-chunk.
// ============================================================
__global__ __launch_bounds__(128) void k_scanC() {
    float* sw = dynsh;             // 3200
    float* se = dynsh + 3200;      // 800
    float* sa = dynsh + 4000;      // 800
    u64*   srp = (u64*)(dynsh + 4800);  // 10*128 u64

    int blk = blockIdx.x;
    int dq = blk & 3;
    int bc = blk >> 2;
    int c = bc % NCHUNK, b = bc / NCHUNK;
    int tid = threadIdx.x;
    int dl = tid >> 3, h = tid & 7;
    int sbase = h * 8;
    int t0 = c * CLEN;

    for (int q = tid; q < CLEN * 14; q += 128) {
        int t = q / 14, p = q % 14;
        sw[t * 64 + 50 + p] = 0.f;
    }

    const float* gw = g_w + ((size_t)b * TT + t0) * SS;
    const float* ge = g_e + ((size_t)b * TT + t0) * DD + dq * 16;
    const float* ga = g_a + ((size_t)b * TT + t0) * DD + dq * 16;
    float* gr = g_r + ((size_t)b * TT + t0) * DD + dq * 16;

    for (int q = tid; q < CLEN * 25; q += 128) {
        int t = q / 25, p = q % 25;
        *(float2*)&sw[t * 64 + 2 * p] = *(const float2*)(gw + (size_t)t * SS + 2 * p);
    }
    for (int q = tid; q < CLEN * 4; q += 128) {
        int t = q >> 2, p = q & 3;
        *(float4*)&se[t * 16 + 4 * p] = *(const float4*)(ge + (size_t)t * DD + 4 * p);
        *(float4*)&sa[t * 16 + 4 * p] = *(const float4*)(ga + (size_t)t * DD + 4 * p);
    }

    u64 mv2[4];
    {
        size_t o = (size_t)blk * 512 + tid * 4;
#pragma unroll
        for (int i = 0; i < 4; ++i) mv2[i] = g_mvb[o + i];
    }
    __syncthreads();

    for (int sub = 0; sub < 5; ++sub) {
#pragma unroll
        for (int tl = 0; tl < 10; ++tl) {
            int t = sub * 10 + tl;
            float e_d = se[t * 16 + dl];
            float a_d = sa[t * 16 + dl];
            u64 ne2 = splat2(-e_d);
            u64 as2 = splat2(a_d);
            ulonglong2 wA = *(const ulonglong2*)&sw[t * 64 + sbase];
            ulonglong2 wB = *(const ulonglong2*)&sw[t * 64 + sbase + 4];
            u64 r2a = ffma2(wA.x, mv2[0], 0ull);
            u64 r2b = ffma2(wA.y, mv2[1], 0ull);
            r2a = ffma2(wB.x, mv2[2], r2a);
            r2b = ffma2(wB.y, mv2[3], r2b);
            srp[tl * 128 + tid] = fadd2(r2a, r2b);
            mv2[0] = ffma2(wA.x, ffma2(mv2[0], ne2, as2), mv2[0]);
            mv2[1] = ffma2(wA.y, ffma2(mv2[1], ne2, as2), mv2[1]);
            mv2[2] = ffma2(wB.x, ffma2(mv2[2], ne2, as2), mv2[2]);
            mv2[3] = ffma2(wB.y, ffma2(mv2[3], ne2, as2), mv2[3]);
        }
        __syncthreads();
#pragma unroll
        for (int o = tid; o < 160; o += 128) {
            int tl = o >> 4, odl = o & 15;
            const u64* pp = srp + tl * 128 + odl * 8;
            u64 s0 = fadd2(pp[0], pp[1]);
            u64 s1 = fadd2(pp[2], pp[3]);
            u64 s2 = fadd2(pp[4], pp[5]);
            u64 s3 = fadd2(pp[6], pp[7]);
            u64 s = fadd2(fadd2(s0, s1), fadd2(s2, s3));
            float2 rr = unpack2(s);
            gr[(size_t)(sub * 10 + tl) * DD + odl] = rr.x + rr.y;
        }
        __syncthreads();
    }
}

// ============================================================
// k_out: grid 250, 2 tiles of 64 tokens. (unchanged from R11 best)
// ============================================================
__global__ __launch_bounds__(256) void k_out(const int* __restrict__ concept,
                                             const float* __restrict__ ek,
                                             const float* __restrict__ Wf,
                                             const float* __restrict__ bf,
                                             const float* __restrict__ Wab,
                                             const float* __restrict__ bab,
                                             const float* __restrict__ Wd,
                                             const float* __restrict__ bd,
                                             float* __restrict__ out) {
    float* sWf = dynsh;
    float* sx  = dynsh + 8192;
    __shared__ int sc_[64];

    int tid = threadIdx.x;
    int td = tid & 15, tt = tid >> 4;

    float4* sWf4w = (float4*)sWf;
    const float4* Wf4 = (const float4*)Wf;
    for (int q = tid; q < 2048; q += 256) sWf4w[q] = Wf4[q];

    float4 bfv = *(const float4*)(bf + 4 * td);
    float4 wabv = *(const float4*)(Wab + 4 * td);
    float4 wdv = *(const float4*)(Wd + 4 * td);
    float bab0 = bab[0], bd0 = bd[0];

    for (int tile = 0; tile < 2; ++tile) {
        int base = (blockIdx.x * 2 + tile) * 64;

        __syncthreads();
        if (tid < 64) sc_[tid] = concept[base + tid];
        __syncthreads();

        float4* sx4 = (float4*)sx;
        const float4* gr4 = (const float4*)g_r;
        const float4* ek4 = (const float4*)ek;
        for (int q = tid; q < 1024; q += 256) {
            int tok = q >> 4, kk = q & 15;
            sx4[tok * 32 + kk] = gr4[(size_t)(base + tok) * 16 + kk];
            sx4[tok * 32 + 16 + kk] = ek4[(size_t)sc_[tok] * 16 + kk];
        }
        __syncthreads();

        const float4* sWf4 = (const float4*)sWf;
        u64 acc[4][2];
#pragma unroll
        for (int j = 0; j < 4; ++j) { acc[j][0] = 0ull; acc[j][1] = 0ull; }

#pragma unroll
        for (int kk = 0; kk < 32; ++kk) {
            ulonglong2 w0 = *(const ulonglong2*)(sWf4 + (4 * kk + 0) * 16 + td);
            ulonglong2 w1 = *(const ulonglong2*)(sWf4 + (4 * kk + 1) * 16 + td);
            ulonglong2 w2 = *(const ulonglong2*)(sWf4 + (4 * kk + 2) * 16 + td);
            ulonglong2 w3 = *(const ulonglong2*)(sWf4 + (4 * kk + 3) * 16 + td);
#pragma unroll
            for (int j = 0; j < 4; ++j) {
                float4 xv = sx4[(tt + 16 * j) * 32 + kk];
                u64 x0 = splat2(xv.x), x1 = splat2(xv.y), x2 = splat2(xv.z), x3 = splat2(xv.w);
                acc[j][0] = ffma2(x0, w0.x, acc[j][0]);
                acc[j][1] = ffma2(x0, w0.y, acc[j][1]);
                acc[j][0] = ffma2(x1, w1.x, acc[j][0]);
                acc[j][1] = ffma2(x1, w1.y, acc[j][1]);
                acc[j][0] = ffma2(x2, w2.x, acc[j][0]);
                acc[j][1] = ffma2(x2, w2.y, acc[j][1]);
                acc[j][0] = ffma2(x3, w3.x, acc[j][0]);
                acc[j][1] = ffma2(x3, w3.y, acc[j][1]);
            }
        }

#pragma unroll
        for (int j = 0; j < 4; ++j) {
            int tok = tt + 16 * j;
            float2 a01 = unpack2(acc[j][0]);
            float2 a23 = unpack2(acc[j][1]);
            float f0 = fast_tanh(a01.x + bfv.x);
            float f1 = fast_tanh(a01.y + bfv.y);
            float f2 = fast_tanh(a23.x + bfv.z);
            float f3 = fast_tanh(a23.y + bfv.w);
            float pa = f0 * wabv.x + f1 * wabv.y + f2 * wabv.z + f3 * wabv.w;
            float4 kd = *(const float4*)&sx[tok * 128 + 64 + 4 * td];
            float pq = kd.x * wdv.x + kd.y * wdv.y + kd.z * wdv.z + kd.w * wdv.w;
#pragma unroll
            for (int o = 8; o > 0; o >>= 1) {
                pa += __shfl_xor_sync(0xffffffffu, pa, o);
                pq += __shfl_xor_sync(0xffffffffu, pq, o);
            }
            if (td == 0) {
                float val = 3.f * fast_tanh(pa + bab0) - fast_tanh(pq + bd0);
                out[base + tok] = fast_sigmoid(val);
            }
        }
    }
}

// ============================================================
extern "C" void kernel_launch(void* const* d_in, const int* in_sizes, int n_in,
                              void* d_out, int out_size) {
    const int*   concept = (const int*)d_in[0];
    const int*   correct = (const int*)d_in[1];
    const int*   nc      = (const int*)d_in[2];
    const float* ek      = (const float*)d_in[3];
    const float* ev      = (const float*)d_in[4];
    const float* Mk      = (const float*)d_in[5];
    const float* Mv0     = (const float*)d_in[6];
    const float* Wf      = (const float*)d_in[7];
    const float* bf      = (const float*)d_in[8];
    const float* We      = (const float*)d_in[9];
    const float* be      = (const float*)d_in[10];
    const float* Wa      = (const float*)d_in[11];
    const float* ba      = (const float*)d_in[12];
    const float* Wab     = (const float*)d_in[13];
    const float* bab     = (const float*)d_in[14];
    const float* Wd      = (const float*)d_in[15];
    const float* bd      = (const float*)d_in[16];
    float* out = (float*)d_out;

    const int FRONT_SMEM = 19760 * sizeof(float);   // ~77KB
    const int SA_SMEM    = 4800 * sizeof(float);    // 19.2KB
    const int SC_SMEM    = 7360 * sizeof(float);    // 29.4KB
    const int OUT_SMEM   = 16384 * sizeof(float);   // 64KB
    cudaFuncSetAttribute(k_front, cudaFuncAttributeMaxDynamicSharedMemorySize, FRONT_SMEM);
    cudaFuncSetAttribute(k_out,   cudaFuncAttributeMaxDynamicSharedMemorySize, OUT_SMEM);

    k_front<<<250, 256, FRONT_SMEM>>>(concept, correct, nc, ek, ev, Mk, We, be, Wa, ba);
    k_scanA<<<NBLK_SCAN, 128, SA_SMEM>>>();
    k_scanB<<<256, 128>>>(Mv0);
    k_scanC<<<NBLK_SCAN, 128, SC_SMEM>>>();
    k_out<<<250, 256, OUT_SMEM>>>(concept, ek, Wf, bf, Wab, bab, Wd, bd, out);
}

// round 13
// speedup vs baseline: 1.0779x; 1.0779x over previous
#include <cuda_runtime.h>
#include <math.h>

#define BB 64
#define TT 500
#define SS 50
#define DD 64
#define NTOK (BB*TT)
#define NCHUNK 10
#define CLEN 50
#define NBLK_SCAN (BB * 4 * NCHUNK)   // 2560

typedef unsigned long long u64;

__device__ float g_w[(size_t)NTOK*SS];
__device__ float g_e[(size_t)NTOK*DD];
__device__ float g_a[(size_t)NTOK*DD];
__device__ float g_r[(size_t)NTOK*DD];
// affine chunk maps + boundary states: [blk(2560)][tid(128)*4]
__device__ u64 gA2[(size_t)NBLK_SCAN*512];
__device__ u64 gB2[(size_t)NBLK_SCAN*512];
__device__ u64 g_mvb[(size_t)NBLK_SCAN*512];

__device__ __forceinline__ float fast_sigmoid(float x) {
    return 1.f / (1.f + __expf(-x));
}
__device__ __forceinline__ float fast_tanh(float x) {
    return fmaf(2.f, fast_sigmoid(2.f * x), -1.f);
}

// ---- packed f32x2 helpers ----
__device__ __forceinline__ u64 ffma2(u64 a, u64 b, u64 c) {
    u64 d;
    asm("fma.rn.f32x2 %0, %1, %2, %3;" : "=l"(d) : "l"(a), "l"(b), "l"(c));
    return d;
}
__device__ __forceinline__ u64 fmul2(u64 a, u64 b) {
    u64 d;
    asm("mul.rn.f32x2 %0, %1, %2;" : "=l"(d) : "l"(a), "l"(b));
    return d;
}
__device__ __forceinline__ u64 fadd2(u64 a, u64 b) {
    u64 d;
    asm("add.rn.f32x2 %0, %1, %2;" : "=l"(d) : "l"(a), "l"(b));
    return d;
}
__device__ __forceinline__ u64 splat2(float x) {
    u64 d;
    asm("mov.b64 %0, {%1, %1};" : "=l"(d) : "r"(__float_as_uint(x)));
    return d;
}
__device__ __forceinline__ u64 pack2(float lo, float hi) {
    u64 d;
    asm("mov.b64 %0, {%1, %2};" : "=l"(d) : "r"(__float_as_uint(lo)), "r"(__float_as_uint(hi)));
    return d;
}
__device__ __forceinline__ float2 unpack2(u64 v) {
    unsigned int lo, hi;
    asm("mov.b64 {%0, %1}, %2;" : "=r"(lo), "=r"(hi) : "l"(v));
    return make_float2(__uint_as_float(lo), __uint_as_float(hi));
}

extern __shared__ float dynsh[];

// ============================================================
// k_front: FUSED scores-softmax + e/a gates. Grid 250, 2 tiles.
// (unchanged, measured 38.5us)
// ============================================================
#define SROW 52
__global__ __launch_bounds__(256) void k_front(const int* __restrict__ concept,
                                               const int* __restrict__ correct,
                                               const int* __restrict__ nc_ptr,
                                               const float* __restrict__ ek,
                                               const float* __restrict__ ev,
                                               const float* __restrict__ Mk,
                                               const float* __restrict__ We,
                                               const float* __restrict__ be,
                                               const float* __restrict__ Wa,
                                               const float* __restrict__ ba) {
    float* sMkT = dynsh;
    float* sWe  = dynsh + 3376;
    float* sWa  = dynsh + 7472;
    float* sxk  = dynsh + 11568;
    float* sxv  = dynsh + 15664;
    __shared__ int sc_[64], sidx[64];

    int tid = threadIdx.x;
    int td = tid & 15, tt = tid >> 4;
    int nc = *nc_ptr;

    for (int q = tid; q < 3376; q += 256) sMkT[q] = 0.f;
    __syncthreads();
    for (int q = tid; q < SS * DD; q += 256) {
        int s = q >> 6, k = q & 63;
        sMkT[k * SROW + s] = Mk[q];
    }
    {
        float4* sWe4w = (float4*)sWe;
        float4* sWa4w = (float4*)sWa;
        const float4* We4 = (const float4*)We;
        const float4* Wa4 = (const float4*)Wa;
        for (int q = tid; q < 1024; q += 256) {
            sWe4w[q] = We4[q];
            sWa4w[q] = Wa4[q];
        }
    }
    float4 bev = *(const float4*)(be + 4 * td);
    float4 bav = *(const float4*)(ba + 4 * td);

    for (int tile = 0; tile < 2; ++tile) {
        int base = (blockIdx.x * 2 + tile) * 64;

        __syncthreads();
        if (tid < 64) {
            int c = concept[base + tid];
            sc_[tid] = c;
            sidx[tid] = c + nc * correct[base + tid];
        }
        __syncthreads();
        {
            float4* sxk4 = (float4*)sxk;
            float4* sxv4 = (float4*)sxv;
            const float4* ek4 = (const float4*)ek;
            const float4* ev4 = (const float4*)ev;
            for (int q = tid; q < 1024; q += 256) {
                int tok = q >> 4, kk = q & 15;
                sxk4[q] = ek4[(size_t)sc_[tok] * 16 + kk];
                sxv4[q] = ev4[(size_t)sidx[tok] * 16 + kk];
            }
        }
        __syncthreads();

        {
            const float4* sM4 = (const float4*)sMkT;
            const float4* sx4 = (const float4*)sxk;
            u64 acc[4][2];
#pragma unroll
            for (int j = 0; j < 4; ++j) { acc[j][0] = 0ull; acc[j][1] = 0ull; }

#pragma unroll
            for (int kk = 0; kk < 16; ++kk) {
                ulonglong2 w0 = *(const ulonglong2*)(sM4 + (4 * kk + 0) * 13 + td);
                ulonglong2 w1 = *(const ulonglong2*)(sM4 + (4 * kk + 1) * 13 + td);
                ulonglong2 w2 = *(const ulonglong2*)(sM4 + (4 * kk + 2) * 13 + td);
                ulonglong2 w3 = *(const ulonglong2*)(sM4 + (4 * kk + 3) * 13 + td);
#pragma unroll
                for (int j = 0; j < 4; ++j) {
                    float4 xv = sx4[(tt + 16 * j) * 16 + kk];
                    u64 x0 = splat2(xv.x), x1 = splat2(xv.y), x2 = splat2(xv.z), x3 = splat2(xv.w);
                    acc[j][0] = ffma2(x0, w0.x, acc[j][0]);
                    acc[j][1] = ffma2(x0, w0.y, acc[j][1]);
                    acc[j][0] = ffma2(x1, w1.x, acc[j][0]);
                    acc[j][1] = ffma2(x1, w1.y, acc[j][1]);
                    acc[j][0] = ffma2(x2, w2.x, acc[j][0]);
                    acc[j][1] = ffma2(x2, w2.y, acc[j][1]);
                    acc[j][0] = ffma2(x3, w3.x, acc[j][0]);
                    acc[j][1] = ffma2(x3, w3.y, acc[j][1]);
                }
            }

#pragma unroll
            for (int j = 0; j < 4; ++j) {
                float2 a01 = unpack2(acc[j][0]);
                float2 a23 = unpack2(acc[j][1]);
                float e0 = (4 * td + 0) < SS ? __expf(a01.x) : 0.f;
                float e1 = (4 * td + 1) < SS ? __expf(a01.y) : 0.f;
                float e2 = (4 * td + 2) < SS ? __expf(a23.x) : 0.f;
                float e3 = (4 * td + 3) < SS ? __expf(a23.y) : 0.f;
                float p = e0 + e1 + e2 + e3;
                p += __shfl_xor_sync(0xffffffffu, p, 1);
                p += __shfl_xor_sync(0xffffffffu, p, 2);
                p += __shfl_xor_sync(0xffffffffu, p, 4);
                p += __shfl_xor_sync(0xffffffffu, p, 8);
                float inv = 1.f / p;
                int tok = base + tt + 16 * j;
                float* gwp = g_w + (size_t)tok * SS + 4 * td;
                if (td < 12) {
                    *(float2*)gwp       = make_float2(e0 * inv, e1 * inv);
                    *(float2*)(gwp + 2) = make_float2(e2 * inv, e3 * inv);
                } else if (td == 12) {
                    *(float2*)gwp       = make_float2(e0 * inv, e1 * inv);
                }
            }
        }

        {
            const float4* sWe4 = (const float4*)sWe;
            const float4* sWa4 = (const float4*)sWa;
            const float4* sx4 = (const float4*)sxv;
            u64 ae[4][2], aa[4][2];
#pragma unroll
            for (int j = 0; j < 4; ++j) {
                ae[j][0] = ae[j][1] = 0ull;
                aa[j][0] = aa[j][1] = 0ull;
            }

#pragma unroll
            for (int kk = 0; kk < 16; ++kk) {
                ulonglong2 e0 = *(const ulonglong2*)(sWe4 + (4 * kk + 0) * 16 + td);
                ulonglong2 e1 = *(const ulonglong2*)(sWe4 + (4 * kk + 1) * 16 + td);
                ulonglong2 e2 = *(const ulonglong2*)(sWe4 + (4 * kk + 2) * 16 + td);
                ulonglong2 e3 = *(const ulonglong2*)(sWe4 + (4 * kk + 3) * 16 + td);
                ulonglong2 a0 = *(const ulonglong2*)(sWa4 + (4 * kk + 0) * 16 + td);
                ulonglong2 a1 = *(const ulonglong2*)(sWa4 + (4 * kk + 1) * 16 + td);
                ulonglong2 a2 = *(const ulonglong2*)(sWa4 + (4 * kk + 2) * 16 + td);
                ulonglong2 a3 = *(const ulonglong2*)(sWa4 + (4 * kk + 3) * 16 + td);
#pragma unroll
                for (int j = 0; j < 4; ++j) {
                    float4 xv = sx4[(tt + 16 * j) * 16 + kk];
                    u64 x0 = splat2(xv.x), x1 = splat2(xv.y), x2 = splat2(xv.z), x3 = splat2(xv.w);
                    ae[j][0] = ffma2(x0, e0.x, ae[j][0]);
                    ae[j][1] = ffma2(x0, e0.y, ae[j][1]);
                    aa[j][0] = ffma2(x0, a0.x, aa[j][0]);
                    aa[j][1] = ffma2(x0, a0.y, aa[j][1]);
                    ae[j][0] = ffma2(x1, e1.x, ae[j][0]);
                    ae[j][1] = ffma2(x1, e1.y, ae[j][1]);
                    aa[j][0] = ffma2(x1, a1.x, aa[j][0]);
                    aa[j][1] = ffma2(x1, a1.y, aa[j][1]);
                    ae[j][0] = ffma2(x2, e2.x, ae[j][0]);
                    ae[j][1] = ffma2(x2, e2.y, ae[j][1]);
                    aa[j][0] = ffma2(x2, a2.x, aa[j][0]);
                    aa[j][1] = ffma2(x2, a2.y, aa[j][1]);
                    ae[j][0] = ffma2(x3, e3.x, ae[j][0]);
                    ae[j][1] = ffma2(x3, e3.y, ae[j][1]);
                    aa[j][0] = ffma2(x3, a3.x, aa[j][0]);
                    aa[j][1] = ffma2(x3, a3.y, aa[j][1]);
                }
            }

#pragma unroll
            for (int j = 0; j < 4; ++j) {
                size_t tok = (size_t)(base + tt + 16 * j);
                float2 ae01 = unpack2(ae[j][0]);
                float2 ae23 = unpack2(ae[j][1]);
                float2 aa01 = unpack2(aa[j][0]);
                float2 aa23 = unpack2(aa[j][1]);
                float4 eo, ao;
                eo.x = fast_sigmoid(ae01.x + bev.x);
                eo.y = fast_sigmoid(ae01.y + bev.y);
                eo.z = fast_sigmoid(ae23.x + bev.z);
                eo.w = fast_sigmoid(ae23.y + bev.w);
                ao.x = fast_tanh(aa01.x + bav.x);
                ao.y = fast_tanh(aa01.y + bav.y);
                ao.z = fast_tanh(aa23.x + bav.z);
                ao.w = fast_tanh(aa23.y + bav.w);
                *(float4*)(g_e + tok * DD + 4 * td) = eo;
                *(float4*)(g_a + tok * DD + 4 * td) = ao;
            }
        }
    }
}

// ============================================================
// Scan phase A: per (b, dq, chunk) block compute affine chunk map.
// (unchanged from R12)
// ============================================================
__global__ __launch_bounds__(128) void k_scanA() {
    float* sw = dynsh;            // 3200
    float* se = dynsh + 3200;     // 800
    float* sa = dynsh + 4000;     // 800

    int blk = blockIdx.x;
    int dq = blk & 3;
    int bc = blk >> 2;
    int c = bc % NCHUNK, b = bc / NCHUNK;
    int tid = threadIdx.x;
    int dl = tid >> 3, h = tid & 7;
    int sbase = h * 8;
    int t0 = c * CLEN;

    for (int q = tid; q < CLEN * 14; q += 128) {
        int t = q / 14, p = q % 14;
        sw[t * 64 + 50 + p] = 0.f;
    }

    const float* gw = g_w + ((size_t)b * TT + t0) * SS;
    const float* ge = g_e + ((size_t)b * TT + t0) * DD + dq * 16;
    const float* ga = g_a + ((size_t)b * TT + t0) * DD + dq * 16;

    for (int q = tid; q < CLEN * 25; q += 128) {
        int t = q / 25, p = q % 25;
        *(float2*)&sw[t * 64 + 2 * p] = *(const float2*)(gw + (size_t)t * SS + 2 * p);
    }
    for (int q = tid; q < CLEN * 4; q += 128) {
        int t = q >> 2, p = q & 3;
        *(float4*)&se[t * 16 + 4 * p] = *(const float4*)(ge + (size_t)t * DD + 4 * p);
        *(float4*)&sa[t * 16 + 4 * p] = *(const float4*)(ga + (size_t)t * DD + 4 * p);
    }
    __syncthreads();

    const u64 ONE2 = splat2(1.f);
    u64 A2[4] = {ONE2, ONE2, ONE2, ONE2};
    u64 B2[4] = {0ull, 0ull, 0ull, 0ull};

#pragma unroll 5
    for (int t = 0; t < CLEN; ++t) {
        float e_d = se[t * 16 + dl];
        float a_d = sa[t * 16 + dl];
        u64 ne2 = splat2(-e_d);
        u64 as2 = splat2(a_d);
        ulonglong2 wA = *(const ulonglong2*)&sw[t * 64 + sbase];
        ulonglong2 wB = *(const ulonglong2*)&sw[t * 64 + sbase + 4];
        u64 f0 = ffma2(wA.x, ne2, ONE2);
        u64 f1 = ffma2(wA.y, ne2, ONE2);
        u64 f2 = ffma2(wB.x, ne2, ONE2);
        u64 f3 = ffma2(wB.y, ne2, ONE2);
        A2[0] = fmul2(A2[0], f0);
        A2[1] = fmul2(A2[1], f1);
        A2[2] = fmul2(A2[2], f2);
        A2[3] = fmul2(A2[3], f3);
        B2[0] = ffma2(B2[0], f0, fmul2(wA.x, as2));
        B2[1] = ffma2(B2[1], f1, fmul2(wA.y, as2));
        B2[2] = ffma2(B2[2], f2, fmul2(wB.x, as2));
        B2[3] = ffma2(B2[3], f3, fmul2(wB.y, as2));
    }

    size_t o = (size_t)blk * 512 + tid * 4;
#pragma unroll
    for (int i = 0; i < 4; ++i) {
        gA2[o + i] = A2[i];
        gB2[o + i] = B2[i];
    }
}

// ============================================================
// Scan phase B: compose chunk maps -> boundary states g_mvb.
// (unchanged from R12)
// ============================================================
__global__ __launch_bounds__(128) void k_scanB(const float* __restrict__ Mv0) {
    int m = blockIdx.x;
    int dq = m & 3, b = m >> 2;
    int tid = threadIdx.x;
    int dl = tid >> 3, h = tid & 7;
    int d = dq * 16 + dl;
    int sbase = h * 8;

    u64 mv2[4];
#pragma unroll
    for (int i = 0; i < 4; ++i) {
        int s0 = sbase + 2 * i, s1 = s0 + 1;
        float lo = (s0 < SS) ? Mv0[s0 * DD + d] : 0.f;
        float hi = (s1 < SS) ? Mv0[s1 * DD + d] : 0.f;
        mv2[i] = pack2(lo, hi);
    }

    for (int c = 0; c < NCHUNK; ++c) {
        size_t o = (size_t)(((b * NCHUNK + c) * 4 + dq)) * 512 + tid * 4;
#pragma unroll
        for (int i = 0; i < 4; ++i) {
            g_mvb[o + i] = mv2[i];
            mv2[i] = ffma2(gA2[o + i], mv2[i], gB2[o + i]);
        }
    }
}

// ============================================================
// Scan phase C: replay each chunk from boundary state, emit r via
// IN-WARP shuffles (8 h-partials are contiguous lanes). NO barriers
// in the loop, NO srp smem. smem: sw 3200 | se 800 | sa 800 = 4800 f.
// ============================================================
__global__ __launch_bounds__(128) void k_scanC() {
    float* sw = dynsh;             // 3200
    float* se = dynsh + 3200;      // 800
    float* sa = dynsh + 4000;      // 800

    int blk = blockIdx.x;
    int dq = blk & 3;
    int bc = blk >> 2;
    int c = bc % NCHUNK, b = bc / NCHUNK;
    int tid = threadIdx.x;
    int dl = tid >> 3, h = tid & 7;
    int sbase = h * 8;
    int t0 = c * CLEN;

    for (int q = tid; q < CLEN * 14; q += 128) {
        int t = q / 14, p = q % 14;
        sw[t * 64 + 50 + p] = 0.f;
    }

    const float* gw = g_w + ((size_t)b * TT + t0) * SS;
    const float* ge = g_e + ((size_t)b * TT + t0) * DD + dq * 16;
    const float* ga = g_a + ((size_t)b * TT + t0) * DD + dq * 16;
    float* gr = g_r + ((size_t)b * TT + t0) * DD + dq * 16;

    for (int q = tid; q < CLEN * 25; q += 128) {
        int t = q / 25, p = q % 25;
        *(float2*)&sw[t * 64 + 2 * p] = *(const float2*)(gw + (size_t)t * SS + 2 * p);
    }
    for (int q = tid; q < CLEN * 4; q += 128) {
        int t = q >> 2, p = q & 3;
        *(float4*)&se[t * 16 + 4 * p] = *(const float4*)(ge + (size_t)t * DD + 4 * p);
        *(float4*)&sa[t * 16 + 4 * p] = *(const float4*)(ga + (size_t)t * DD + 4 * p);
    }

    u64 mv2[4];
    {
        size_t o = (size_t)blk * 512 + tid * 4;
#pragma unroll
        for (int i = 0; i < 4; ++i) mv2[i] = g_mvb[o + i];
    }
    __syncthreads();

#pragma unroll 5
    for (int t = 0; t < CLEN; ++t) {
        float e_d = se[t * 16 + dl];
        float a_d = sa[t * 16 + dl];
        u64 ne2 = splat2(-e_d);
        u64 as2 = splat2(a_d);
        ulonglong2 wA = *(const ulonglong2*)&sw[t * 64 + sbase];
        ulonglong2 wB = *(const ulonglong2*)&sw[t * 64 + sbase + 4];
        u64 r2a = ffma2(wA.x, mv2[0], 0ull);
        u64 r2b = ffma2(wA.y, mv2[1], 0ull);
        r2a = ffma2(wB.x, mv2[2], r2a);
        r2b = ffma2(wB.y, mv2[3], r2b);
        mv2[0] = ffma2(wA.x, ffma2(mv2[0], ne2, as2), mv2[0]);
        mv2[1] = ffma2(wA.y, ffma2(mv2[1], ne2, as2), mv2[1]);
        mv2[2] = ffma2(wB.x, ffma2(mv2[2], ne2, as2), mv2[2]);
        mv2[3] = ffma2(wB.y, ffma2(mv2[3], ne2, as2), mv2[3]);
        float2 rr = unpack2(fadd2(r2a, r2b));
        float r = rr.x + rr.y;
        r += __shfl_xor_sync(0xffffffffu, r, 1);
        r += __shfl_xor_sync(0xffffffffu, r, 2);
        r += __shfl_xor_sync(0xffffffffu, r, 4);
        if (h == 0) gr[(size_t)t * DD + dl] = r;
    }
}

// ============================================================
// k_out: grid 250, 2 tiles of 64 tokens. (unchanged, ~28us)
// ============================================================
__global__ __launch_bounds__(256) void k_out(const int* __restrict__ concept,
                                             const float* __restrict__ ek,
                                             const float* __restrict__ Wf,
                                             const float* __restrict__ bf,
                                             const float* __restrict__ Wab,
                                             const float* __restrict__ bab,
                                             const float* __restrict__ Wd,
                                             const float* __restrict__ bd,
                                             float* __restrict__ out) {
    float* sWf = dynsh;
    float* sx  = dynsh + 8192;
    __shared__ int sc_[64];

    int tid = threadIdx.x;
    int td = tid & 15, tt = tid >> 4;

    float4* sWf4w = (float4*)sWf;
    const float4* Wf4 = (const float4*)Wf;
    for (int q = tid; q < 2048; q += 256) sWf4w[q] = Wf4[q];

    float4 bfv = *(const float4*)(bf + 4 * td);
    float4 wabv = *(const float4*)(Wab + 4 * td);
    float4 wdv = *(const float4*)(Wd + 4 * td);
    float bab0 = bab[0], bd0 = bd[0];

    for (int tile = 0; tile < 2; ++tile) {
        int base = (blockIdx.x * 2 + tile) * 64;

        __syncthreads();
        if (tid < 64) sc_[tid] = concept[base + tid];
        __syncthreads();

        float4* sx4 = (float4*)sx;
        const float4* gr4 = (const float4*)g_r;
        const float4* ek4 = (const float4*)ek;
        for (int q = tid; q < 1024; q += 256) {
            int tok = q >> 4, kk = q & 15;
            sx4[tok * 32 + kk] = gr4[(size_t)(base + tok) * 16 + kk];
            sx4[tok * 32 + 16 + kk] = ek4[(size_t)sc_[tok] * 16 + kk];
        }
        __syncthreads();

        const float4* sWf4 = (const float4*)sWf;
        u64 acc[4][2];
#pragma unroll
        for (int j = 0; j < 4; ++j) { acc[j][0] = 0ull; acc[j][1] = 0ull; }

#pragma unroll
        for (int kk = 0; kk < 32; ++kk) {
            ulonglong2 w0 = *(const ulonglong2*)(sWf4 + (4 * kk + 0) * 16 + td);
            ulonglong2 w1 = *(const ulonglong2*)(sWf4 + (4 * kk + 1) * 16 + td);
            ulonglong2 w2 = *(const ulonglong2*)(sWf4 + (4 * kk + 2) * 16 + td);
            ulonglong2 w3 = *(const ulonglong2*)(sWf4 + (4 * kk + 3) * 16 + td);
#pragma unroll
            for (int j = 0; j < 4; ++j) {
                float4 xv = sx4[(tt + 16 * j) * 32 + kk];
                u64 x0 = splat2(xv.x), x1 = splat2(xv.y), x2 = splat2(xv.z), x3 = splat2(xv.w);
                acc[j][0] = ffma2(x0, w0.x, acc[j][0]);
                acc[j][1] = ffma2(x0, w0.y, acc[j][1]);
                acc[j][0] = ffma2(x1, w1.x, acc[j][0]);
                acc[j][1] = ffma2(x1, w1.y, acc[j][1]);
                acc[j][0] = ffma2(x2, w2.x, acc[j][0]);
                acc[j][1] = ffma2(x2, w2.y, acc[j][1]);
                acc[j][0] = ffma2(x3, w3.x, acc[j][0]);
                acc[j][1] = ffma2(x3, w3.y, acc[j][1]);
            }
        }

#pragma unroll
        for (int j = 0; j < 4; ++j) {
            int tok = tt + 16 * j;
            float2 a01 = unpack2(acc[j][0]);
            float2 a23 = unpack2(acc[j][1]);
            float f0 = fast_tanh(a01.x + bfv.x);
            float f1 = fast_tanh(a01.y + bfv.y);
            float f2 = fast_tanh(a23.x + bfv.z);
            float f3 = fast_tanh(a23.y + bfv.w);
            float pa = f0 * wabv.x + f1 * wabv.y + f2 * wabv.z + f3 * wabv.w;
            float4 kd = *(const float4*)&sx[tok * 128 + 64 + 4 * td];
            float pq = kd.x * wdv.x + kd.y * wdv.y + kd.z * wdv.z + kd.w * wdv.w;
#pragma unroll
            for (int o = 8; o > 0; o >>= 1) {
                pa += __shfl_xor_sync(0xffffffffu, pa, o);
                pq += __shfl_xor_sync(0xffffffffu, pq, o);
            }
            if (td == 0) {
                float val = 3.f * fast_tanh(pa + bab0) - fast_tanh(pq + bd0);
                out[base + tok] = fast_sigmoid(val);
            }
        }
    }
}

// ============================================================
extern "C" void kernel_launch(void* const* d_in, const int* in_sizes, int n_in,
                              void* d_out, int out_size) {
    const int*   concept = (const int*)d_in[0];
    const int*   correct = (const int*)d_in[1];
    const int*   nc      = (const int*)d_in[2];
    const float* ek      = (const float*)d_in[3];
    const float* ev      = (const float*)d_in[4];
    const float* Mk      = (const float*)d_in[5];
    const float* Mv0     = (const float*)d_in[6];
    const float* Wf      = (const float*)d_in[7];
    const float* bf      = (const float*)d_in[8];
    const float* We      = (const float*)d_in[9];
    const float* be      = (const float*)d_in[10];
    const float* Wa      = (const float*)d_in[11];
    const float* ba      = (const float*)d_in[12];
    const float* Wab     = (const float*)d_in[13];
    const float* bab     = (const float*)d_in[14];
    const float* Wd      = (const float*)d_in[15];
    const float* bd      = (const float*)d_in[16];
    float* out = (float*)d_out;

    const int FRONT_SMEM = 19760 * sizeof(float);   // ~77KB
    const int SA_SMEM    = 4800 * sizeof(float);    // 19.2KB
    const int SC_SMEM    = 4800 * sizeof(float);    // 19.2KB
    const int OUT_SMEM   = 16384 * sizeof(float);   // 64KB
    cudaFuncSetAttribute(k_front, cudaFuncAttributeMaxDynamicSharedMemorySize, FRONT_SMEM);
    cudaFuncSetAttribute(k_out,   cudaFuncAttributeMaxDynamicSharedMemorySize, OUT_SMEM);

    k_front<<<250, 256, FRONT_SMEM>>>(concept, correct, nc, ek, ev, Mk, We, be, Wa, ba);
    k_scanA<<<NBLK_SCAN, 128, SA_SMEM>>>();
    k_scanB<<<256, 128>>>(Mv0);
    k_scanC<<<NBLK_SCAN, 128, SC_SMEM>>>();
    k_out<<<250, 256, OUT_SMEM>>>(concept, ek, Wf, bf, Wab, bab, Wd, bd, out);
}

// round 14
// speedup vs baseline: 1.2769x; 1.1847x over previous
#include <cuda_runtime.h>
#include <math.h>

#define BB 64
#define TT 500
#define SS 50
#define DD 64
#define NTOK (BB*TT)

typedef unsigned long long u64;

__device__ float g_w[(size_t)NTOK*SS];
__device__ float g_e[(size_t)NTOK*DD];
__device__ float g_a[(size_t)NTOK*DD];
__device__ float g_r[(size_t)NTOK*DD];

__device__ __forceinline__ float fast_sigmoid(float x) {
    return 1.f / (1.f + __expf(-x));
}
__device__ __forceinline__ float fast_tanh(float x) {
    return fmaf(2.f, fast_sigmoid(2.f * x), -1.f);
}

// ---- packed f32x2 helpers ----
__device__ __forceinline__ u64 ffma2(u64 a, u64 b, u64 c) {
    u64 d;
    asm("fma.rn.f32x2 %0, %1, %2, %3;" : "=l"(d) : "l"(a), "l"(b), "l"(c));
    return d;
}
__device__ __forceinline__ u64 fadd2(u64 a, u64 b) {
    u64 d;
    asm("add.rn.f32x2 %0, %1, %2;" : "=l"(d) : "l"(a), "l"(b));
    return d;
}
__device__ __forceinline__ u64 splat2(float x) {
    u64 d;
    asm("mov.b64 %0, {%1, %1};" : "=l"(d) : "r"(__float_as_uint(x)));
    return d;
}
__device__ __forceinline__ u64 pack2(float lo, float hi) {
    u64 d;
    asm("mov.b64 %0, {%1, %2};" : "=l"(d) : "r"(__float_as_uint(lo)), "r"(__float_as_uint(hi)));
    return d;
}
__device__ __forceinline__ float2 unpack2(u64 v) {
    unsigned int lo, hi;
    asm("mov.b64 {%0, %1}, %2;" : "=r"(lo), "=r"(hi) : "l"(v));
    return make_float2(__uint_as_float(lo), __uint_as_float(hi));
}

extern __shared__ float dynsh[];

// ============================================================
// k_front: FUSED scores-softmax + e/a gates. Grid 250, 2 tiles.
// (R11-best, measured 38.5us)
// ============================================================
#define SROW 52
__global__ __launch_bounds__(256) void k_front(const int* __restrict__ concept,
                                               const int* __restrict__ correct,
                                               const int* __restrict__ nc_ptr,
                                               const float* __restrict__ ek,
                                               const float* __restrict__ ev,
                                               const float* __restrict__ Mk,
                                               const float* __restrict__ We,
                                               const float* __restrict__ be,
                                               const float* __restrict__ Wa,
                                               const float* __restrict__ ba) {
    float* sMkT = dynsh;
    float* sWe  = dynsh + 3376;
    float* sWa  = dynsh + 7472;
    float* sxk  = dynsh + 11568;
    float* sxv  = dynsh + 15664;
    __shared__ int sc_[64], sidx[64];

    int tid = threadIdx.x;
    int td = tid & 15, tt = tid >> 4;
    int nc = *nc_ptr;

    for (int q = tid; q < 3376; q += 256) sMkT[q] = 0.f;
    __syncthreads();
    for (int q = tid; q < SS * DD; q += 256) {
        int s = q >> 6, k = q & 63;
        sMkT[k * SROW + s] = Mk[q];
    }
    {
        float4* sWe4w = (float4*)sWe;
        float4* sWa4w = (float4*)sWa;
        const float4* We4 = (const float4*)We;
        const float4* Wa4 = (const float4*)Wa;
        for (int q = tid; q < 1024; q += 256) {
            sWe4w[q] = We4[q];
            sWa4w[q] = Wa4[q];
        }
    }
    float4 bev = *(const float4*)(be + 4 * td);
    float4 bav = *(const float4*)(ba + 4 * td);

    for (int tile = 0; tile < 2; ++tile) {
        int base = (blockIdx.x * 2 + tile) * 64;

        __syncthreads();
        if (tid < 64) {
            int c = concept[base + tid];
            sc_[tid] = c;
            sidx[tid] = c + nc * correct[base + tid];
        }
        __syncthreads();
        {
            float4* sxk4 = (float4*)sxk;
            float4* sxv4 = (float4*)sxv;
            const float4* ek4 = (const float4*)ek;
            const float4* ev4 = (const float4*)ev;
            for (int q = tid; q < 1024; q += 256) {
                int tok = q >> 4, kk = q & 15;
                sxk4[q] = ek4[(size_t)sc_[tok] * 16 + kk];
                sxv4[q] = ev4[(size_t)sidx[tok] * 16 + kk];
            }
        }
        __syncthreads();

        {
            const float4* sM4 = (const float4*)sMkT;
            const float4* sx4 = (const float4*)sxk;
            u64 acc[4][2];
#pragma unroll
            for (int j = 0; j < 4; ++j) { acc[j][0] = 0ull; acc[j][1] = 0ull; }

#pragma unroll
            for (int kk = 0; kk < 16; ++kk) {
                ulonglong2 w0 = *(const ulonglong2*)(sM4 + (4 * kk + 0) * 13 + td);
                ulonglong2 w1 = *(const ulonglong2*)(sM4 + (4 * kk + 1) * 13 + td);
                ulonglong2 w2 = *(const ulonglong2*)(sM4 + (4 * kk + 2) * 13 + td);
                ulonglong2 w3 = *(const ulonglong2*)(sM4 + (4 * kk + 3) * 13 + td);
#pragma unroll
                for (int j = 0; j < 4; ++j) {
                    float4 xv = sx4[(tt + 16 * j) * 16 + kk];
                    u64 x0 = splat2(xv.x), x1 = splat2(xv.y), x2 = splat2(xv.z), x3 = splat2(xv.w);
                    acc[j][0] = ffma2(x0, w0.x, acc[j][0]);
                    acc[j][1] = ffma2(x0, w0.y, acc[j][1]);
                    acc[j][0] = ffma2(x1, w1.x, acc[j][0]);
                    acc[j][1] = ffma2(x1, w1.y, acc[j][1]);
                    acc[j][0] = ffma2(x2, w2.x, acc[j][0]);
                    acc[j][1] = ffma2(x2, w2.y, acc[j][1]);
                    acc[j][0] = ffma2(x3, w3.x, acc[j][0]);
                    acc[j][1] = ffma2(x3, w3.y, acc[j][1]);
                }
            }

#pragma unroll
            for (int j = 0; j < 4; ++j) {
                float2 a01 = unpack2(acc[j][0]);
                float2 a23 = unpack2(acc[j][1]);
                float e0 = (4 * td + 0) < SS ? __expf(a01.x) : 0.f;
                float e1 = (4 * td + 1) < SS ? __expf(a01.y) : 0.f;
                float e2 = (4 * td + 2) < SS ? __expf(a23.x) : 0.f;
                float e3 = (4 * td + 3) < SS ? __expf(a23.y) : 0.f;
                float p = e0 + e1 + e2 + e3;
                p += __shfl_xor_sync(0xffffffffu, p, 1);
                p += __shfl_xor_sync(0xffffffffu, p, 2);
                p += __shfl_xor_sync(0xffffffffu, p, 4);
                p += __shfl_xor_sync(0xffffffffu, p, 8);
                float inv = 1.f / p;
                int tok = base + tt + 16 * j;
                float* gwp = g_w + (size_t)tok * SS + 4 * td;
                if (td < 12) {
                    *(float2*)gwp       = make_float2(e0 * inv, e1 * inv);
                    *(float2*)(gwp + 2) = make_float2(e2 * inv, e3 * inv);
                } else if (td == 12) {
                    *(float2*)gwp       = make_float2(e0 * inv, e1 * inv);
                }
            }
        }

        {
            const float4* sWe4 = (const float4*)sWe;
            const float4* sWa4 = (const float4*)sWa;
            const float4* sx4 = (const float4*)sxv;
            u64 ae[4][2], aa[4][2];
#pragma unroll
            for (int j = 0; j < 4; ++j) {
                ae[j][0] = ae[j][1] = 0ull;
                aa[j][0] = aa[j][1] = 0ull;
            }

#pragma unroll
            for (int kk = 0; kk < 16; ++kk) {
                ulonglong2 e0 = *(const ulonglong2*)(sWe4 + (4 * kk + 0) * 16 + td);
                ulonglong2 e1 = *(const ulonglong2*)(sWe4 + (4 * kk + 1) * 16 + td);
                ulonglong2 e2 = *(const ulonglong2*)(sWe4 + (4 * kk + 2) * 16 + td);
                ulonglong2 e3 = *(const ulonglong2*)(sWe4 + (4 * kk + 3) * 16 + td);
                ulonglong2 a0 = *(const ulonglong2*)(sWa4 + (4 * kk + 0) * 16 + td);
                ulonglong2 a1 = *(const ulonglong2*)(sWa4 + (4 * kk + 1) * 16 + td);
                ulonglong2 a2 = *(const ulonglong2*)(sWa4 + (4 * kk + 2) * 16 + td);
                ulonglong2 a3 = *(const ulonglong2*)(sWa4 + (4 * kk + 3) * 16 + td);
#pragma unroll
                for (int j = 0; j < 4; ++j) {
                    float4 xv = sx4[(tt + 16 * j) * 16 + kk];
                    u64 x0 = splat2(xv.x), x1 = splat2(xv.y), x2 = splat2(xv.z), x3 = splat2(xv.w);
                    ae[j][0] = ffma2(x0, e0.x, ae[j][0]);
                    ae[j][1] = ffma2(x0, e0.y, ae[j][1]);
                    aa[j][0] = ffma2(x0, a0.x, aa[j][0]);
                    aa[j][1] = ffma2(x0, a0.y, aa[j][1]);
                    ae[j][0] = ffma2(x1, e1.x, ae[j][0]);
                    ae[j][1] = ffma2(x1, e1.y, ae[j][1]);
                    aa[j][0] = ffma2(x1, a1.x, aa[j][0]);
                    aa[j][1] = ffma2(x1, a1.y, aa[j][1]);
                    ae[j][0] = ffma2(x2, e2.x, ae[j][0]);
                    ae[j][1] = ffma2(x2, e2.y, ae[j][1]);
                    aa[j][0] = ffma2(x2, a2.x, aa[j][0]);
                    aa[j][1] = ffma2(x2, a2.y, aa[j][1]);
                    ae[j][0] = ffma2(x3, e3.x, ae[j][0]);
                    ae[j][1] = ffma2(x3, e3.y, ae[j][1]);
                    aa[j][0] = ffma2(x3, a3.x, aa[j][0]);
                    aa[j][1] = ffma2(x3, a3.y, aa[j][1]);
                }
            }

#pragma unroll
            for (int j = 0; j < 4; ++j) {
                size_t tok = (size_t)(base + tt + 16 * j);
                float2 ae01 = unpack2(ae[j][0]);
                float2 ae23 = unpack2(ae[j][1]);
                float2 aa01 = unpack2(aa[j][0]);
                float2 aa23 = unpack2(aa[j][1]);
                float4 eo, ao;
                eo.x = fast_sigmoid(ae01.x + bev.x);
                eo.y = fast_sigmoid(ae01.y + bev.y);
                eo.z = fast_sigmoid(ae23.x + bev.z);
                eo.w = fast_sigmoid(ae23.y + bev.w);
                ao.x = fast_tanh(aa01.x + bav.x);
                ao.y = fast_tanh(aa01.y + bav.y);
                ao.z = fast_tanh(aa23.x + bav.z);
                ao.w = fast_tanh(aa23.y + bav.w);
                *(float4*)(g_e + tok * DD + 4 * td) = eo;
                *(float4*)(g_a + tok * DD + 4 * td) = ao;
            }
        }
    }
}

// ============================================================
// k_scan: serial scan, 16 s-states per thread (mv2[8] packed).
// 128 blocks = (b, d-half: 32 dims), 128 thr: dl = tid>>2 (32),
// h = tid&3 (4 groups x 16 s, padded 50->64). CH=20 double-buffered,
// 2 barriers/chunk (50 total). In-warp 2-shuffle r reduction.
// Static smem 20KB.
// ============================================================
#define CH 20
__global__ __launch_bounds__(128) void k_scan(const float* __restrict__ Mv0) {
    __shared__ __align__(16) float sw[2][CH][64];
    __shared__ __align__(16) float se[2][CH][32];
    __shared__ __align__(16) float sa[2][CH][32];

    int b = blockIdx.x >> 1, half = blockIdx.x & 1;
    int tid = threadIdx.x;
    int dl = tid >> 2, h = tid & 3;
    int d = half * 32 + dl;
    int sbase = h * 16;

    // zero w pads (s in [50,64)) for both buffers
    for (int q = tid; q < 2 * CH * 14; q += 128) {
        int bf = q / (CH * 14), rem = q % (CH * 14), t = rem / 14, p = rem % 14;
        sw[bf][t][50 + p] = 0.f;
    }

    u64 mv2[8];
#pragma unroll
    for (int i = 0; i < 8; ++i) {
        int s0 = sbase + 2 * i, s1 = s0 + 1;
        float lo = (s0 < SS) ? Mv0[s0 * DD + d] : 0.f;
        float hi = (s1 < SS) ? Mv0[s1 * DD + d] : 0.f;
        mv2[i] = pack2(lo, hi);
    }

    const float* gw = g_w + (size_t)b * TT * SS;
    const float* ge = g_e + (size_t)b * TT * DD + half * 32;
    const float* ga = g_a + (size_t)b * TT * DD + half * 32;
    float* gr = g_r + (size_t)b * TT * DD + half * 32;

    // staging: w = CH*25 = 500 float2 (4/thread); e/a = CH*8 = 160 float4 (2/thread)
    float2 wreg[4];
    float4 ereg[2], areg[2];

#pragma unroll
    for (int n = 0; n < 4; n++) {
        int q = tid + 128 * n;
        if (q < CH * 25) { int t = q / 25, p = q % 25; wreg[n] = *(const float2*)(gw + (size_t)t * SS + 2 * p); }
    }
#pragma unroll
    for (int n = 0; n < 2; n++) {
        int q = tid + 128 * n;
        if (q < CH * 8) {
            int t = q >> 3, p = q & 7;
            ereg[n] = *(const float4*)(ge + (size_t)t * DD + 4 * p);
            areg[n] = *(const float4*)(ga + (size_t)t * DD + 4 * p);
        }
    }
#pragma unroll
    for (int n = 0; n < 4; n++) {
        int q = tid + 128 * n;
        if (q < CH * 25) { int t = q / 25, p = q % 25; *(float2*)&sw[0][t][2 * p] = wreg[n]; }
    }
#pragma unroll
    for (int n = 0; n < 2; n++) {
        int q = tid + 128 * n;
        if (q < CH * 8) {
            int t = q >> 3, p = q & 7;
            *(float4*)&se[0][t][4 * p] = ereg[n];
            *(float4*)&sa[0][t][4 * p] = areg[n];
        }
    }
    __syncthreads();

    for (int c = 0; c < TT / CH; ++c) {
        int cur = c & 1;
        if (c < TT / CH - 1) {
            int t0 = (c + 1) * CH;
#pragma unroll
            for (int n = 0; n < 4; n++) {
                int q = tid + 128 * n;
                if (q < CH * 25) { int t = q / 25, p = q % 25; wreg[n] = *(const float2*)(gw + (size_t)(t0 + t) * SS + 2 * p); }
            }
#pragma unroll
            for (int n = 0; n < 2; n++) {
                int q = tid + 128 * n;
                if (q < CH * 8) {
                    int t = q >> 3, p = q & 7;
                    ereg[n] = *(const float4*)(ge + (size_t)(t0 + t) * DD + 4 * p);
                    areg[n] = *(const float4*)(ga + (size_t)(t0 + t) * DD + 4 * p);
                }
            }
        }

        int t0 = c * CH;
#pragma unroll
        for (int tl = 0; tl < CH; ++tl) {
            float e_d = se[cur][tl][dl];
            float a_d = sa[cur][tl][dl];
            u64 ne2 = splat2(-e_d);
            u64 as2 = splat2(a_d);
            const ulonglong2* wp = (const ulonglong2*)&sw[cur][tl][sbase];
            ulonglong2 w01 = wp[0];
            ulonglong2 w23 = wp[1];
            ulonglong2 w45 = wp[2];
            ulonglong2 w67 = wp[3];

            u64 r0 = ffma2(w01.x, mv2[0], 0ull);
            u64 r1 = ffma2(w01.y, mv2[1], 0ull);
            r0 = ffma2(w23.x, mv2[2], r0);
            r1 = ffma2(w23.y, mv2[3], r1);
            r0 = ffma2(w45.x, mv2[4], r0);
            r1 = ffma2(w45.y, mv2[5], r1);
            r0 = ffma2(w67.x, mv2[6], r0);
            r1 = ffma2(w67.y, mv2[7], r1);

            mv2[0] = ffma2(w01.x, ffma2(mv2[0], ne2, as2), mv2[0]);
            mv2[1] = ffma2(w01.y, ffma2(mv2[1], ne2, as2), mv2[1]);
            mv2[2] = ffma2(w23.x, ffma2(mv2[2], ne2, as2), mv2[2]);
            mv2[3] = ffma2(w23.y, ffma2(mv2[3], ne2, as2), mv2[3]);
            mv2[4] = ffma2(w45.x, ffma2(mv2[4], ne2, as2), mv2[4]);
            mv2[5] = ffma2(w45.y, ffma2(mv2[5], ne2, as2), mv2[5]);
            mv2[6] = ffma2(w67.x, ffma2(mv2[6], ne2, as2), mv2[6]);
            mv2[7] = ffma2(w67.y, ffma2(mv2[7], ne2, as2), mv2[7]);

            float2 rr = unpack2(fadd2(r0, r1));
            float r = rr.x + rr.y;
            r += __shfl_xor_sync(0xffffffffu, r, 1);
            r += __shfl_xor_sync(0xffffffffu, r, 2);
            if (h == 0) gr[(size_t)(t0 + tl) * DD + dl] = r;
        }
        __syncthreads();

        if (c < TT / CH - 1) {
            int nb = cur ^ 1;
#pragma unroll
            for (int n = 0; n < 4; n++) {
                int q = tid + 128 * n;
                if (q < CH * 25) { int t = q / 25, p = q % 25; *(float2*)&sw[nb][t][2 * p] = wreg[n]; }
            }
#pragma unroll
            for (int n = 0; n < 2; n++) {
                int q = tid + 128 * n;
                if (q < CH * 8) {
                    int t = q >> 3, p = q & 7;
                    *(float4*)&se[nb][t][4 * p] = ereg[n];
                    *(float4*)&sa[nb][t][4 * p] = areg[n];
                }
            }
        }
        __syncthreads();
    }
}

// ============================================================
// k_out: grid 250, 2 tiles of 64 tokens. (R11-best, ~28us)
// ============================================================
__global__ __launch_bounds__(256) void k_out(const int* __restrict__ concept,
                                             const float* __restrict__ ek,
                                             const float* __restrict__ Wf,
                                             const float* __restrict__ bf,
                                             const float* __restrict__ Wab,
                                             const float* __restrict__ bab,
                                             const float* __restrict__ Wd,
                                             const float* __restrict__ bd,
                                             float* __restrict__ out) {
    float* sWf = dynsh;
    float* sx  = dynsh + 8192;
    __shared__ int sc_[64];

    int tid = threadIdx.x;
    int td = tid & 15, tt = tid >> 4;

    float4* sWf4w = (float4*)sWf;
    const float4* Wf4 = (const float4*)Wf;
    for (int q = tid; q < 2048; q += 256) sWf4w[q] = Wf4[q];

    float4 bfv = *(const float4*)(bf + 4 * td);
    float4 wabv = *(const float4*)(Wab + 4 * td);
    float4 wdv = *(const float4*)(Wd + 4 * td);
    float bab0 = bab[0], bd0 = bd[0];

    for (int tile = 0; tile < 2; ++tile) {
        int base = (blockIdx.x * 2 + tile) * 64;

        __syncthreads();
        if (tid < 64) sc_[tid] = concept[base + tid];
        __syncthreads();

        float4* sx4 = (float4*)sx;
        const float4* gr4 = (const float4*)g_r;
        const float4* ek4 = (const float4*)ek;
        for (int q = tid; q < 1024; q += 256) {
            int tok = q >> 4, kk = q & 15;
            sx4[tok * 32 + kk] = gr4[(size_t)(base + tok) * 16 + kk];
            sx4[tok * 32 + 16 + kk] = ek4[(size_t)sc_[tok] * 16 + kk];
        }
        __syncthreads();

        const float4* sWf4 = (const float4*)sWf;
        u64 acc[4][2];
#pragma unroll
        for (int j = 0; j < 4; ++j) { acc[j][0] = 0ull; acc[j][1] = 0ull; }

#pragma unroll
        for (int kk = 0; kk < 32; ++kk) {
            ulonglong2 w0 = *(const ulonglong2*)(sWf4 + (4 * kk + 0) * 16 + td);
            ulonglong2 w1 = *(const ulonglong2*)(sWf4 + (4 * kk + 1) * 16 + td);
            ulonglong2 w2 = *(const ulonglong2*)(sWf4 + (4 * kk + 2) * 16 + td);
            ulonglong2 w3 = *(const ulonglong2*)(sWf4 + (4 * kk + 3) * 16 + td);
#pragma unroll
            for (int j = 0; j < 4; ++j) {
                float4 xv = sx4[(tt + 16 * j) * 32 + kk];
                u64 x0 = splat2(xv.x), x1 = splat2(xv.y), x2 = splat2(xv.z), x3 = splat2(xv.w);
                acc[j][0] = ffma2(x0, w0.x, acc[j][0]);
                acc[j][1] = ffma2(x0, w0.y, acc[j][1]);
                acc[j][0] = ffma2(x1, w1.x, acc[j][0]);
                acc[j][1] = ffma2(x1, w1.y, acc[j][1]);
                acc[j][0] = ffma2(x2, w2.x, acc[j][0]);
                acc[j][1] = ffma2(x2, w2.y, acc[j][1]);
                acc[j][0] = ffma2(x3, w3.x, acc[j][0]);
                acc[j][1] = ffma2(x3, w3.y, acc[j][1]);
            }
        }

#pragma unroll
        for (int j = 0; j < 4; ++j) {
            int tok = tt + 16 * j;
            float2 a01 = unpack2(acc[j][0]);
            float2 a23 = unpack2(acc[j][1]);
            float f0 = fast_tanh(a01.x + bfv.x);
            float f1 = fast_tanh(a01.y + bfv.y);
            float f2 = fast_tanh(a23.x + bfv.z);
            float f3 = fast_tanh(a23.y + bfv.w);
            float pa = f0 * wabv.x + f1 * wabv.y + f2 * wabv.z + f3 * wabv.w;
            float4 kd = *(const float4*)&sx[tok * 128 + 64 + 4 * td];
            float pq = kd.x * wdv.x + kd.y * wdv.y + kd.z * wdv.z + kd.w * wdv.w;
#pragma unroll
            for (int o = 8; o > 0; o >>= 1) {
                pa += __shfl_xor_sync(0xffffffffu, pa, o);
                pq += __shfl_xor_sync(0xffffffffu, pq, o);
            }
            if (td == 0) {
                float val = 3.f * fast_tanh(pa + bab0) - fast_tanh(pq + bd0);
                out[base + tok] = fast_sigmoid(val);
            }
        }
    }
}

// ============================================================
extern "C" void kernel_launch(void* const* d_in, const int* in_sizes, int n_in,
                              void* d_out, int out_size) {
    const int*   concept = (const int*)d_in[0];
    const int*   correct = (const int*)d_in[1];
    const int*   nc      = (const int*)d_in[2];
    const float* ek      = (const float*)d_in[3];
    const float* ev      = (const float*)d_in[4];
    const float* Mk      = (const float*)d_in[5];
    const float* Mv0     = (const float*)d_in[6];
    const float* Wf      = (const float*)d_in[7];
    const float* bf      = (const float*)d_in[8];
    const float* We      = (const float*)d_in[9];
    const float* be      = (const float*)d_in[10];
    const float* Wa      = (const float*)d_in[11];
    const float* ba      = (const float*)d_in[12];
    const float* Wab     = (const float*)d_in[13];
    const float* bab     = (const float*)d_in[14];
    const float* Wd      = (const float*)d_in[15];
    const float* bd      = (const float*)d_in[16];
    float* out = (float*)d_out;

    const int FRONT_SMEM = 19760 * sizeof(float);   // ~77KB
    const int OUT_SMEM   = 16384 * sizeof(float);   // 64KB
    cudaFuncSetAttribute(k_front, cudaFuncAttributeMaxDynamicSharedMemorySize, FRONT_SMEM);
    cudaFuncSetAttribute(k_out,   cudaFuncAttributeMaxDynamicSharedMemorySize, OUT_SMEM);

    k_front<<<250, 256, FRONT_SMEM>>>(concept, correct, nc, ek, ev, Mk, We, be, Wa, ba);
    k_scan<<<128, 128>>>(Mv0);
    k_out<<<250, 256, OUT_SMEM>>>(concept, ek, Wf, bf, Wab, bab, Wd, bd, out);
}

// round 15
// speedup vs baseline: 1.4614x; 1.1444x over previous
#include <cuda_runtime.h>
#include <math.h>

#define BB 64
#define TT 500
#define SS 50
#define DD 64
#define NTOK (BB*TT)

typedef unsigned long long u64;

__device__ float g_w[(size_t)NTOK*SS];
__device__ float g_e[(size_t)NTOK*DD];
__device__ float g_a[(size_t)NTOK*DD];
__device__ float g_r[(size_t)NTOK*DD];

__device__ __forceinline__ float fast_sigmoid(float x) {
    return 1.f / (1.f + __expf(-x));
}
__device__ __forceinline__ float fast_tanh(float x) {
    return fmaf(2.f, fast_sigmoid(2.f * x), -1.f);
}

// ---- packed f32x2 helpers ----
__device__ __forceinline__ u64 ffma2(u64 a, u64 b, u64 c) {
    u64 d;
    asm("fma.rn.f32x2 %0, %1, %2, %3;" : "=l"(d) : "l"(a), "l"(b), "l"(c));
    return d;
}
__device__ __forceinline__ u64 fadd2(u64 a, u64 b) {
    u64 d;
    asm("add.rn.f32x2 %0, %1, %2;" : "=l"(d) : "l"(a), "l"(b));
    return d;
}
__device__ __forceinline__ u64 splat2(float x) {
    u64 d;
    asm("mov.b64 %0, {%1, %1};" : "=l"(d) : "r"(__float_as_uint(x)));
    return d;
}
__device__ __forceinline__ u64 pack2(float lo, float hi) {
    u64 d;
    asm("mov.b64 %0, {%1, %2};" : "=l"(d) : "r"(__float_as_uint(lo)), "r"(__float_as_uint(hi)));
    return d;
}
__device__ __forceinline__ float2 unpack2(u64 v) {
    unsigned int lo, hi;
    asm("mov.b64 {%0, %1}, %2;" : "=r"(lo), "=r"(hi) : "l"(v));
    return make_float2(__uint_as_float(lo), __uint_as_float(hi));
}

extern __shared__ float dynsh[];

// ============================================================
// k_front: FUSED scores-softmax + e/a gates. Grid 250, 2 tiles.
// (R11-best, measured 38.5us — unchanged)
// ============================================================
#define SROW 52
__global__ __launch_bounds__(256) void k_front(const int* __restrict__ concept,
                                               const int* __restrict__ correct,
                                               const int* __restrict__ nc_ptr,
                                               const float* __restrict__ ek,
                                               const float* __restrict__ ev,
                                               const float* __restrict__ Mk,
                                               const float* __restrict__ We,
                                               const float* __restrict__ be,
                                               const float* __restrict__ Wa,
                                               const float* __restrict__ ba) {
    float* sMkT = dynsh;
    float* sWe  = dynsh + 3376;
    float* sWa  = dynsh + 7472;
    float* sxk  = dynsh + 11568;
    float* sxv  = dynsh + 15664;
    __shared__ int sc_[64], sidx[64];

    int tid = threadIdx.x;
    int td = tid & 15, tt = tid >> 4;
    int nc = *nc_ptr;

    for (int q = tid; q < 3376; q += 256) sMkT[q] = 0.f;
    __syncthreads();
    for (int q = tid; q < SS * DD; q += 256) {
        int s = q >> 6, k = q & 63;
        sMkT[k * SROW + s] = Mk[q];
    }
    {
        float4* sWe4w = (float4*)sWe;
        float4* sWa4w = (float4*)sWa;
        const float4* We4 = (const float4*)We;
        const float4* Wa4 = (const float4*)Wa;
        for (int q = tid; q < 1024; q += 256) {
            sWe4w[q] = We4[q];
            sWa4w[q] = Wa4[q];
        }
    }
    float4 bev = *(const float4*)(be + 4 * td);
    float4 bav = *(const float4*)(ba + 4 * td);

    for (int tile = 0; tile < 2; ++tile) {
        int base = (blockIdx.x * 2 + tile) * 64;

        __syncthreads();
        if (tid < 64) {
            int c = concept[base + tid];
            sc_[tid] = c;
            sidx[tid] = c + nc * correct[base + tid];
        }
        __syncthreads();
        {
            float4* sxk4 = (float4*)sxk;
            float4* sxv4 = (float4*)sxv;
            const float4* ek4 = (const float4*)ek;
            const float4* ev4 = (const float4*)ev;
            for (int q = tid; q < 1024; q += 256) {
                int tok = q >> 4, kk = q & 15;
                sxk4[q] = ek4[(size_t)sc_[tok] * 16 + kk];
                sxv4[q] = ev4[(size_t)sidx[tok] * 16 + kk];
            }
        }
        __syncthreads();

        {
            const float4* sM4 = (const float4*)sMkT;
            const float4* sx4 = (const float4*)sxk;
            u64 acc[4][2];
#pragma unroll
            for (int j = 0; j < 4; ++j) { acc[j][0] = 0ull; acc[j][1] = 0ull; }

#pragma unroll
            for (int kk = 0; kk < 16; ++kk) {
                ulonglong2 w0 = *(const ulonglong2*)(sM4 + (4 * kk + 0) * 13 + td);
                ulonglong2 w1 = *(const ulonglong2*)(sM4 + (4 * kk + 1) * 13 + td);
                ulonglong2 w2 = *(const ulonglong2*)(sM4 + (4 * kk + 2) * 13 + td);
                ulonglong2 w3 = *(const ulonglong2*)(sM4 + (4 * kk + 3) * 13 + td);
#pragma unroll
                for (int j = 0; j < 4; ++j) {
                    float4 xv = sx4[(tt + 16 * j) * 16 + kk];
                    u64 x0 = splat2(xv.x), x1 = splat2(xv.y), x2 = splat2(xv.z), x3 = splat2(xv.w);
                    acc[j][0] = ffma2(x0, w0.x, acc[j][0]);
                    acc[j][1] = ffma2(x0, w0.y, acc[j][1]);
                    acc[j][0] = ffma2(x1, w1.x, acc[j][0]);
                    acc[j][1] = ffma2(x1, w1.y, acc[j][1]);
                    acc[j][0] = ffma2(x2, w2.x, acc[j][0]);
                    acc[j][1] = ffma2(x2, w2.y, acc[j][1]);
                    acc[j][0] = ffma2(x3, w3.x, acc[j][0]);
                    acc[j][1] = ffma2(x3, w3.y, acc[j][1]);
                }
            }

#pragma unroll
            for (int j = 0; j < 4; ++j) {
                float2 a01 = unpack2(acc[j][0]);
                float2 a23 = unpack2(acc[j][1]);
                float e0 = (4 * td + 0) < SS ? __expf(a01.x) : 0.f;
                float e1 = (4 * td + 1) < SS ? __expf(a01.y) : 0.f;
                float e2 = (4 * td + 2) < SS ? __expf(a23.x) : 0.f;
                float e3 = (4 * td + 3) < SS ? __expf(a23.y) : 0.f;
                float p = e0 + e1 + e2 + e3;
                p += __shfl_xor_sync(0xffffffffu, p, 1);
                p += __shfl_xor_sync(0xffffffffu, p, 2);
                p += __shfl_xor_sync(0xffffffffu, p, 4);
                p += __shfl_xor_sync(0xffffffffu, p, 8);
                float inv = 1.f / p;
                int tok = base + tt + 16 * j;
                float* gwp = g_w + (size_t)tok * SS + 4 * td;
                if (td < 12) {
                    *(float2*)gwp       = make_float2(e0 * inv, e1 * inv);
                    *(float2*)(gwp + 2) = make_float2(e2 * inv, e3 * inv);
                } else if (td == 12) {
                    *(float2*)gwp       = make_float2(e0 * inv, e1 * inv);
                }
            }
        }

        {
            const float4* sWe4 = (const float4*)sWe;
            const float4* sWa4 = (const float4*)sWa;
            const float4* sx4 = (const float4*)sxv;
            u64 ae[4][2], aa[4][2];
#pragma unroll
            for (int j = 0; j < 4; ++j) {
                ae[j][0] = ae[j][1] = 0ull;
                aa[j][0] = aa[j][1] = 0ull;
            }

#pragma unroll
            for (int kk = 0; kk < 16; ++kk) {
                ulonglong2 e0 = *(const ulonglong2*)(sWe4 + (4 * kk + 0) * 16 + td);
                ulonglong2 e1 = *(const ulonglong2*)(sWe4 + (4 * kk + 1) * 16 + td);
                ulonglong2 e2 = *(const ulonglong2*)(sWe4 + (4 * kk + 2) * 16 + td);
                ulonglong2 e3 = *(const ulonglong2*)(sWe4 + (4 * kk + 3) * 16 + td);
                ulonglong2 a0 = *(const ulonglong2*)(sWa4 + (4 * kk + 0) * 16 + td);
                ulonglong2 a1 = *(const ulonglong2*)(sWa4 + (4 * kk + 1) * 16 + td);
                ulonglong2 a2 = *(const ulonglong2*)(sWa4 + (4 * kk + 2) * 16 + td);
                ulonglong2 a3 = *(const ulonglong2*)(sWa4 + (4 * kk + 3) * 16 + td);
#pragma unroll
                for (int j = 0; j < 4; ++j) {
                    float4 xv = sx4[(tt + 16 * j) * 16 + kk];
                    u64 x0 = splat2(xv.x), x1 = splat2(xv.y), x2 = splat2(xv.z), x3 = splat2(xv.w);
                    ae[j][0] = ffma2(x0, e0.x, ae[j][0]);
                    ae[j][1] = ffma2(x0, e0.y, ae[j][1]);
                    aa[j][0] = ffma2(x0, a0.x, aa[j][0]);
                    aa[j][1] = ffma2(x0, a0.y, aa[j][1]);
                    ae[j][0] = ffma2(x1, e1.x, ae[j][0]);
                    ae[j][1] = ffma2(x1, e1.y, ae[j][1]);
                    aa[j][0] = ffma2(x1, a1.x, aa[j][0]);
                    aa[j][1] = ffma2(x1, a1.y, aa[j][1]);
                    ae[j][0] = ffma2(x2, e2.x, ae[j][0]);
                    ae[j][1] = ffma2(x2, e2.y, ae[j][1]);
                    aa[j][0] = ffma2(x2, a2.x, aa[j][0]);
                    aa[j][1] = ffma2(x2, a2.y, aa[j][1]);
                    ae[j][0] = ffma2(x3, e3.x, ae[j][0]);
                    ae[j][1] = ffma2(x3, e3.y, ae[j][1]);
                    aa[j][0] = ffma2(x3, a3.x, aa[j][0]);
                    aa[j][1] = ffma2(x3, a3.y, aa[j][1]);
                }
            }

#pragma unroll
            for (int j = 0; j < 4; ++j) {
                size_t tok = (size_t)(base + tt + 16 * j);
                float2 ae01 = unpack2(ae[j][0]);
                float2 ae23 = unpack2(ae[j][1]);
                float2 aa01 = unpack2(aa[j][0]);
                float2 aa23 = unpack2(aa[j][1]);
                float4 eo, ao;
                eo.x = fast_sigmoid(ae01.x + bev.x);
                eo.y = fast_sigmoid(ae01.y + bev.y);
                eo.z = fast_sigmoid(ae23.x + bev.z);
                eo.w = fast_sigmoid(ae23.y + bev.w);
                ao.x = fast_tanh(aa01.x + bav.x);
                ao.y = fast_tanh(aa01.y + bav.y);
                ao.z = fast_tanh(aa23.x + bav.z);
                ao.w = fast_tanh(aa23.y + bav.w);
                *(float4*)(g_e + tok * DD + 4 * td) = eo;
                *(float4*)(g_a + tok * DD + 4 * td) = ao;
            }
        }
    }
}

// ============================================================
// k_scan: 256 blocks = (b, dq: 16 dims), 128 thr: dl=tid>>3 (16),
// h=tid&7 (8 s-states, padded 50->64). CH=20 double-buffered with
// ONE barrier per chunk; in-warp 3-shuffle r reduction (no srp smem).
// Static smem ~30KB.
// ============================================================
#define CH 20
__global__ __launch_bounds__(128) void k_scan(const float* __restrict__ Mv0) {
    __shared__ __align__(16) float sw[2][CH][64];
    __shared__ __align__(16) float se[2][CH][16];
    __shared__ __align__(16) float sa[2][CH][16];

    int b = blockIdx.x >> 2, dq = blockIdx.x & 3;
    int tid = threadIdx.x;
    int dl = tid >> 3, h = tid & 7;
    int d = dq * 16 + dl;
    int sbase = h * 8;

    // zero w pads (s in [50,64)) for both buffers
    for (int q = tid; q < 2 * CH * 14; q += 128) {
        int bf = q / (CH * 14), rem = q % (CH * 14), t = rem / 14, p = rem % 14;
        sw[bf][t][50 + p] = 0.f;
    }

    u64 mv2[4];
#pragma unroll
    for (int i = 0; i < 4; ++i) {
        int s0 = sbase + 2 * i, s1 = s0 + 1;
        float lo = (s0 < SS) ? Mv0[s0 * DD + d] : 0.f;
        float hi = (s1 < SS) ? Mv0[s1 * DD + d] : 0.f;
        mv2[i] = pack2(lo, hi);
    }

    const float* gw = g_w + (size_t)b * TT * SS;
    const float* ge = g_e + (size_t)b * TT * DD + dq * 16;
    const float* ga = g_a + (size_t)b * TT * DD + dq * 16;
    float* gr = g_r + (size_t)b * TT * DD + dq * 16;

    // staging roles: w = CH*25 = 500 float2 (4/thread);
    // e: CH*4 = 80 float4 (tid<80); a: 80 float4 (tid>=48)
    float2 wreg[4];
    float4 eareg, areg;
    bool do_e = tid < 80;
    bool do_a2 = tid >= 48;
    int et = tid >> 2, ep = tid & 3;
    int at = (tid - 48) >> 2, ap = (tid - 48) & 3;

#pragma unroll
    for (int n = 0; n < 4; n++) {
        int q = tid + 128 * n;
        if (q < CH * 25) { int t = q / 25, p = q % 25; wreg[n] = *(const float2*)(gw + (size_t)t * SS + 2 * p); }
    }
    if (do_e)  eareg = *(const float4*)(ge + (size_t)et * DD + 4 * ep);
    if (do_a2) areg  = *(const float4*)(ga + (size_t)at * DD + 4 * ap);

#pragma unroll
    for (int n = 0; n < 4; n++) {
        int q = tid + 128 * n;
        if (q < CH * 25) { int t = q / 25, p = q % 25; *(float2*)&sw[0][t][2 * p] = wreg[n]; }
    }
    if (do_e)  *(float4*)&se[0][et][4 * ep] = eareg;
    if (do_a2) *(float4*)&sa[0][at][4 * ap] = areg;
    __syncthreads();

    for (int c = 0; c < TT / CH; ++c) {
        int cur = c & 1;
        if (c < TT / CH - 1) {
            int t0 = (c + 1) * CH;
#pragma unroll
            for (int n = 0; n < 4; n++) {
                int q = tid + 128 * n;
                if (q < CH * 25) { int t = q / 25, p = q % 25; wreg[n] = *(const float2*)(gw + (size_t)(t0 + t) * SS + 2 * p); }
            }
            if (do_e)  eareg = *(const float4*)(ge + (size_t)(t0 + et) * DD + 4 * ep);
            if (do_a2) areg  = *(const float4*)(ga + (size_t)(t0 + at) * DD + 4 * ap);
        }

        int t0 = c * CH;
#pragma unroll
        for (int tl = 0; tl < CH; ++tl) {
            float e_d = se[cur][tl][dl];
            float a_d = sa[cur][tl][dl];
            u64 ne2 = splat2(-e_d);
            u64 as2 = splat2(a_d);
            ulonglong2 wA = *(const ulonglong2*)&sw[cur][tl][sbase];
            ulonglong2 wB = *(const ulonglong2*)&sw[cur][tl][sbase + 4];
            u64 r2a = ffma2(wA.x, mv2[0], 0ull);
            u64 r2b = ffma2(wA.y, mv2[1], 0ull);
            r2a = ffma2(wB.x, mv2[2], r2a);
            r2b = ffma2(wB.y, mv2[3], r2b);
            mv2[0] = ffma2(wA.x, ffma2(mv2[0], ne2, as2), mv2[0]);
            mv2[1] = ffma2(wA.y, ffma2(mv2[1], ne2, as2), mv2[1]);
            mv2[2] = ffma2(wB.x, ffma2(mv2[2], ne2, as2), mv2[2]);
            mv2[3] = ffma2(wB.y, ffma2(mv2[3], ne2, as2), mv2[3]);
            float2 rr = unpack2(fadd2(r2a, r2b));
            float r = rr.x + rr.y;
            r += __shfl_xor_sync(0xffffffffu, r, 1);
            r += __shfl_xor_sync(0xffffffffu, r, 2);
            r += __shfl_xor_sync(0xffffffffu, r, 4);
            if (h == 0) gr[(size_t)(t0 + tl) * DD + dl] = r;
        }

        // write prefetched chunk into the other buffer; reads of that
        // buffer completed before the previous chunk's barrier.
        if (c < TT / CH - 1) {
            int nb = cur ^ 1;
#pragma unroll
            for (int n = 0; n < 4; n++) {
                int q = tid + 128 * n;
                if (q < CH * 25) { int t = q / 25, p = q % 25; *(float2*)&sw[nb][t][2 * p] = wreg[n]; }
            }
            if (do_e)  *(float4*)&se[nb][et][4 * ep] = eareg;
            if (do_a2) *(float4*)&sa[nb][at][4 * ap] = areg;
        }
        __syncthreads();
    }
}

// ============================================================
// k_out: grid 250, 2 tiles of 64 tokens. (R11-best, ~28us — unchanged)
// ============================================================
__global__ __launch_bounds__(256) void k_out(const int* __restrict__ concept,
                                             const float* __restrict__ ek,
                                             const float* __restrict__ Wf,
                                             const float* __restrict__ bf,
                                             const float* __restrict__ Wab,
                                             const float* __restrict__ bab,
                                             const float* __restrict__ Wd,
                                             const float* __restrict__ bd,
                                             float* __restrict__ out) {
    float* sWf = dynsh;
    float* sx  = dynsh + 8192;
    __shared__ int sc_[64];

    int tid = threadIdx.x;
    int td = tid & 15, tt = tid >> 4;

    float4* sWf4w = (float4*)sWf;
    const float4* Wf4 = (const float4*)Wf;
    for (int q = tid; q < 2048; q += 256) sWf4w[q] = Wf4[q];

    float4 bfv = *(const float4*)(bf + 4 * td);
    float4 wabv = *(const float4*)(Wab + 4 * td);
    float4 wdv = *(const float4*)(Wd + 4 * td);
    float bab0 = bab[0], bd0 = bd[0];

    for (int tile = 0; tile < 2; ++tile) {
        int base = (blockIdx.x * 2 + tile) * 64;

        __syncthreads();
        if (tid < 64) sc_[tid] = concept[base + tid];
        __syncthreads();

        float4* sx4 = (float4*)sx;
        const float4* gr4 = (const float4*)g_r;
        const float4* ek4 = (const float4*)ek;
        for (int q = tid; q < 1024; q += 256) {
            int tok = q >> 4, kk = q & 15;
            sx4[tok * 32 + kk] = gr4[(size_t)(base + tok) * 16 + kk];
            sx4[tok * 32 + 16 + kk] = ek4[(size_t)sc_[tok] * 16 + kk];
        }
        __syncthreads();

        const float4* sWf4 = (const float4*)sWf;
        u64 acc[4][2];
#pragma unroll
        for (int j = 0; j < 4; ++j) { acc[j][0] = 0ull; acc[j][1] = 0ull; }

#pragma unroll
        for (int kk = 0; kk < 32; ++kk) {
            ulonglong2 w0 = *(const ulonglong2*)(sWf4 + (4 * kk + 0) * 16 + td);
            ulonglong2 w1 = *(const ulonglong2*)(sWf4 + (4 * kk + 1) * 16 + td);
            ulonglong2 w2 = *(const ulonglong2*)(sWf4 + (4 * kk + 2) * 16 + td);
            ulonglong2 w3 = *(const ulonglong2*)(sWf4 + (4 * kk + 3) * 16 + td);
#pragma unroll
            for (int j = 0; j < 4; ++j) {
                float4 xv = sx4[(tt + 16 * j) * 32 + kk];
                u64 x0 = splat2(xv.x), x1 = splat2(xv.y), x2 = splat2(xv.z), x3 = splat2(xv.w);
                acc[j][0] = ffma2(x0, w0.x, acc[j][0]);
                acc[j][1] = ffma2(x0, w0.y, acc[j][1]);
                acc[j][0] = ffma2(x1, w1.x, acc[j][0]);
                acc[j][1] = ffma2(x1, w1.y, acc[j][1]);
                acc[j][0] = ffma2(x2, w2.x, acc[j][0]);
                acc[j][1] = ffma2(x2, w2.y, acc[j][1]);
                acc[j][0] = ffma2(x3, w3.x, acc[j][0]);
                acc[j][1] = ffma2(x3, w3.y, acc[j][1]);
            }
        }

#pragma unroll
        for (int j = 0; j < 4; ++j) {
            int tok = tt + 16 * j;
            float2 a01 = unpack2(acc[j][0]);
            float2 a23 = unpack2(acc[j][1]);
            float f0 = fast_tanh(a01.x + bfv.x);
            float f1 = fast_tanh(a01.y + bfv.y);
            float f2 = fast_tanh(a23.x + bfv.z);
            float f3 = fast_tanh(a23.y + bfv.w);
            float pa = f0 * wabv.x + f1 * wabv.y + f2 * wabv.z + f3 * wabv.w;
            float4 kd = *(const float4*)&sx[tok * 128 + 64 + 4 * td];
            float pq = kd.x * wdv.x + kd.y * wdv.y + kd.z * wdv.z + kd.w * wdv.w;
#pragma unroll
            for (int o = 8; o > 0; o >>= 1) {
                pa += __shfl_xor_sync(0xffffffffu, pa, o);
                pq += __shfl_xor_sync(0xffffffffu, pq, o);
            }
            if (td == 0) {
                float val = 3.f * fast_tanh(pa + bab0) - fast_tanh(pq + bd0);
                out[base + tok] = fast_sigmoid(val);
            }
        }
    }
}

// ============================================================
extern "C" void kernel_launch(void* const* d_in, const int* in_sizes, int n_in,
                              void* d_out, int out_size) {
    const int*   concept = (const int*)d_in[0];
    const int*   correct = (const int*)d_in[1];
    const int*   nc      = (const int*)d_in[2];
    const float* ek      = (const float*)d_in[3];
    const float* ev      = (const float*)d_in[4];
    const float* Mk      = (const float*)d_in[5];
    const float* Mv0     = (const float*)d_in[6];
    const float* Wf      = (const float*)d_in[7];
    const float* bf      = (const float*)d_in[8];
    const float* We      = (const float*)d_in[9];
    const float* be      = (const float*)d_in[10];
    const float* Wa      = (const float*)d_in[11];
    const float* ba      = (const float*)d_in[12];
    const float* Wab     = (const float*)d_in[13];
    const float* bab     = (const float*)d_in[14];
    const float* Wd      = (const float*)d_in[15];
    const float* bd      = (const float*)d_in[16];
    float* out = (float*)d_out;

    const int FRONT_SMEM = 19760 * sizeof(float);   // ~77KB
    const int OUT_SMEM   = 16384 * sizeof(float);   // 64KB
    cudaFuncSetAttribute(k_front, cudaFuncAttributeMaxDynamicSharedMemorySize, FRONT_SMEM);
    cudaFuncSetAttribute(k_out,   cudaFuncAttributeMaxDynamicSharedMemorySize, OUT_SMEM);

    k_front<<<250, 256, FRONT_SMEM>>>(concept, correct, nc, ek, ev, Mk, We, be, Wa, ba);
    k_scan<<<256, 128>>>(Mv0);
    k_out<<<250, 256, OUT_SMEM>>>(concept, ek, Wf, bf, Wab, bab, Wd, bd, out);
}

// round 16
// speedup vs baseline: 1.4659x; 1.0031x over previous
#include <cuda_runtime.h>
#include <math.h>

#define BB 64
#define TT 500
#define SS 50
#define DD 64
#define NTOK (BB*TT)

typedef unsigned long long u64;

__device__ float g_w[(size_t)NTOK*SS];
__device__ float g_e[(size_t)NTOK*DD];
__device__ float g_a[(size_t)NTOK*DD];
__device__ float g_r[(size_t)NTOK*DD];

__device__ __forceinline__ float fast_sigmoid(float x) {
    return 1.f / (1.f + __expf(-x));
}
__device__ __forceinline__ float fast_tanh(float x) {
    return fmaf(2.f, fast_sigmoid(2.f * x), -1.f);
}

// ---- packed f32x2 helpers ----
__device__ __forceinline__ u64 ffma2(u64 a, u64 b, u64 c) {
    u64 d;
    asm("fma.rn.f32x2 %0, %1, %2, %3;" : "=l"(d) : "l"(a), "l"(b), "l"(c));
    return d;
}
__device__ __forceinline__ u64 fadd2(u64 a, u64 b) {
    u64 d;
    asm("add.rn.f32x2 %0, %1, %2;" : "=l"(d) : "l"(a), "l"(b));
    return d;
}
__device__ __forceinline__ u64 splat2(float x) {
    u64 d;
    asm("mov.b64 %0, {%1, %1};" : "=l"(d) : "r"(__float_as_uint(x)));
    return d;
}
__device__ __forceinline__ u64 pack2(float lo, float hi) {
    u64 d;
    asm("mov.b64 %0, {%1, %2};" : "=l"(d) : "r"(__float_as_uint(lo)), "r"(__float_as_uint(hi)));
    return d;
}
__device__ __forceinline__ float2 unpack2(u64 v) {
    unsigned int lo, hi;
    asm("mov.b64 {%0, %1}, %2;" : "=r"(lo), "=r"(hi) : "l"(v));
    return make_float2(__uint_as_float(lo), __uint_as_float(hi));
}

extern __shared__ float dynsh[];

// ============================================================
// k_front: FUSED scores-softmax + e/a gates, with MERGED compute
// loop (scores + e + a in one kk pass for 3x ILP). Grid 250, 2 tiles.
// ============================================================
#define SROW 52
__global__ __launch_bounds__(256) void k_front(const int* __restrict__ concept,
                                               const int* __restrict__ correct,
                                               const int* __restrict__ nc_ptr,
                                               const float* __restrict__ ek,
                                               const float* __restrict__ ev,
                                               const float* __restrict__ Mk,
                                               const float* __restrict__ We,
                                               const float* __restrict__ be,
                                               const float* __restrict__ Wa,
                                               const float* __restrict__ ba) {
    float* sMkT = dynsh;
    float* sWe  = dynsh + 3376;
    float* sWa  = dynsh + 7472;
    float* sxk  = dynsh + 11568;
    float* sxv  = dynsh + 15664;
    __shared__ int sc_[64], sidx[64];

    int tid = threadIdx.x;
    int td = tid & 15, tt = tid >> 4;
    int nc = *nc_ptr;

    for (int q = tid; q < 3376; q += 256) sMkT[q] = 0.f;
    __syncthreads();
    for (int q = tid; q < SS * DD; q += 256) {
        int s = q >> 6, k = q & 63;
        sMkT[k * SROW + s] = Mk[q];
    }
    {
        float4* sWe4w = (float4*)sWe;
        float4* sWa4w = (float4*)sWa;
        const float4* We4 = (const float4*)We;
        const float4* Wa4 = (const float4*)Wa;
        for (int q = tid; q < 1024; q += 256) {
            sWe4w[q] = We4[q];
            sWa4w[q] = Wa4[q];
        }
    }
    float4 bev = *(const float4*)(be + 4 * td);
    float4 bav = *(const float4*)(ba + 4 * td);

    for (int tile = 0; tile < 2; ++tile) {
        int base = (blockIdx.x * 2 + tile) * 64;

        __syncthreads();
        if (tid < 64) {
            int c = concept[base + tid];
            sc_[tid] = c;
            sidx[tid] = c + nc * correct[base + tid];
        }
        __syncthreads();
        {
            float4* sxk4 = (float4*)sxk;
            float4* sxv4 = (float4*)sxv;
            const float4* ek4 = (const float4*)ek;
            const float4* ev4 = (const float4*)ev;
            for (int q = tid; q < 1024; q += 256) {
                int tok = q >> 4, kk = q & 15;
                sxk4[q] = ek4[(size_t)sc_[tok] * 16 + kk];
                sxv4[q] = ev4[(size_t)sidx[tok] * 16 + kk];
            }
        }
        __syncthreads();

        const float4* sM4  = (const float4*)sMkT;
        const float4* sxk4 = (const float4*)sxk;
        const float4* sxv4 = (const float4*)sxv;
        const float4* sWe4 = (const float4*)sWe;
        const float4* sWa4 = (const float4*)sWa;

        u64 acc[4][2], ae[4][2], aa[4][2];
#pragma unroll
        for (int j = 0; j < 4; ++j) {
            acc[j][0] = acc[j][1] = 0ull;
            ae[j][0] = ae[j][1] = 0ull;
            aa[j][0] = aa[j][1] = 0ull;
        }

        // ---- MERGED kk loop: scores + e-gate + a-gate ----
#pragma unroll
        for (int kk = 0; kk < 16; ++kk) {
            ulonglong2 m0 = *(const ulonglong2*)(sM4 + (4 * kk + 0) * 13 + td);
            ulonglong2 m1 = *(const ulonglong2*)(sM4 + (4 * kk + 1) * 13 + td);
            ulonglong2 m2 = *(const ulonglong2*)(sM4 + (4 * kk + 2) * 13 + td);
            ulonglong2 m3 = *(const ulonglong2*)(sM4 + (4 * kk + 3) * 13 + td);
            ulonglong2 e0 = *(const ulonglong2*)(sWe4 + (4 * kk + 0) * 16 + td);
            ulonglong2 e1 = *(const ulonglong2*)(sWe4 + (4 * kk + 1) * 16 + td);
            ulonglong2 e2 = *(const ulonglong2*)(sWe4 + (4 * kk + 2) * 16 + td);
            ulonglong2 e3 = *(const ulonglong2*)(sWe4 + (4 * kk + 3) * 16 + td);
            ulonglong2 a0 = *(const ulonglong2*)(sWa4 + (4 * kk + 0) * 16 + td);
            ulonglong2 a1 = *(const ulonglong2*)(sWa4 + (4 * kk + 1) * 16 + td);
            ulonglong2 a2 = *(const ulonglong2*)(sWa4 + (4 * kk + 2) * 16 + td);
            ulonglong2 a3 = *(const ulonglong2*)(sWa4 + (4 * kk + 3) * 16 + td);
#pragma unroll
            for (int j = 0; j < 4; ++j) {
                float4 xk = sxk4[(tt + 16 * j) * 16 + kk];
                float4 xv = sxv4[(tt + 16 * j) * 16 + kk];
                u64 k0 = splat2(xk.x), k1 = splat2(xk.y), k2 = splat2(xk.z), k3 = splat2(xk.w);
                u64 v0 = splat2(xv.x), v1 = splat2(xv.y), v2 = splat2(xv.z), v3 = splat2(xv.w);
                acc[j][0] = ffma2(k0, m0.x, acc[j][0]);
                acc[j][1] = ffma2(k0, m0.y, acc[j][1]);
                ae[j][0]  = ffma2(v0, e0.x, ae[j][0]);
                ae[j][1]  = ffma2(v0, e0.y, ae[j][1]);
                aa[j][0]  = ffma2(v0, a0.x, aa[j][0]);
                aa[j][1]  = ffma2(v0, a0.y, aa[j][1]);
                acc[j][0] = ffma2(k1, m1.x, acc[j][0]);
                acc[j][1] = ffma2(k1, m1.y, acc[j][1]);
                ae[j][0]  = ffma2(v1, e1.x, ae[j][0]);
                ae[j][1]  = ffma2(v1, e1.y, ae[j][1]);
                aa[j][0]  = ffma2(v1, a1.x, aa[j][0]);
                aa[j][1]  = ffma2(v1, a1.y, aa[j][1]);
                acc[j][0] = ffma2(k2, m2.x, acc[j][0]);
                acc[j][1] = ffma2(k2, m2.y, acc[j][1]);
                ae[j][0]  = ffma2(v2, e2.x, ae[j][0]);
                ae[j][1]  = ffma2(v2, e2.y, ae[j][1]);
                aa[j][0]  = ffma2(v2, a2.x, aa[j][0]);
                aa[j][1]  = ffma2(v2, a2.y, aa[j][1]);
                acc[j][0] = ffma2(k3, m3.x, acc[j][0]);
                acc[j][1] = ffma2(k3, m3.y, acc[j][1]);
                ae[j][0]  = ffma2(v3, e3.x, ae[j][0]);
                ae[j][1]  = ffma2(v3, e3.y, ae[j][1]);
                aa[j][0]  = ffma2(v3, a3.x, aa[j][0]);
                aa[j][1]  = ffma2(v3, a3.y, aa[j][1]);
            }
        }

        // ---- softmax epilogue ----
#pragma unroll
        for (int j = 0; j < 4; ++j) {
            float2 a01 = unpack2(acc[j][0]);
            float2 a23 = unpack2(acc[j][1]);
            float s0 = (4 * td + 0) < SS ? __expf(a01.x) : 0.f;
            float s1 = (4 * td + 1) < SS ? __expf(a01.y) : 0.f;
            float s2 = (4 * td + 2) < SS ? __expf(a23.x) : 0.f;
            float s3 = (4 * td + 3) < SS ? __expf(a23.y) : 0.f;
            float p = s0 + s1 + s2 + s3;
            p += __shfl_xor_sync(0xffffffffu, p, 1);
            p += __shfl_xor_sync(0xffffffffu, p, 2);
            p += __shfl_xor_sync(0xffffffffu, p, 4);
            p += __shfl_xor_sync(0xffffffffu, p, 8);
            float inv = 1.f / p;
            int tok = base + tt + 16 * j;
            float* gwp = g_w + (size_t)tok * SS + 4 * td;
            if (td < 12) {
                *(float2*)gwp       = make_float2(s0 * inv, s1 * inv);
                *(float2*)(gwp + 2) = make_float2(s2 * inv, s3 * inv);
            } else if (td == 12) {
                *(float2*)gwp       = make_float2(s0 * inv, s1 * inv);
            }
        }

        // ---- gate epilogue ----
#pragma unroll
        for (int j = 0; j < 4; ++j) {
            size_t tok = (size_t)(base + tt + 16 * j);
            float2 ae01 = unpack2(ae[j][0]);
            float2 ae23 = unpack2(ae[j][1]);
            float2 aa01 = unpack2(aa[j][0]);
            float2 aa23 = unpack2(aa[j][1]);
            float4 eo, ao;
            eo.x = fast_sigmoid(ae01.x + bev.x);
            eo.y = fast_sigmoid(ae01.y + bev.y);
            eo.z = fast_sigmoid(ae23.x + bev.z);
            eo.w = fast_sigmoid(ae23.y + bev.w);
            ao.x = fast_tanh(aa01.x + bav.x);
            ao.y = fast_tanh(aa01.y + bav.y);
            ao.z = fast_tanh(aa23.x + bav.z);
            ao.w = fast_tanh(aa23.y + bav.w);
            *(float4*)(g_e + tok * DD + 4 * td) = eo;
            *(float4*)(g_a + tok * DD + 4 * td) = ao;
        }
    }
}

// ============================================================
// k_scan: R15-best (115.2us config) — unchanged.
// 256 blocks = (b, dq), 128 thr, CH=20, 1 barrier/chunk,
// in-warp 3-shuffle reduction.
// ============================================================
#define CH 20
__global__ __launch_bounds__(128) void k_scan(const float* __restrict__ Mv0) {
    __shared__ __align__(16) float sw[2][CH][64];
    __shared__ __align__(16) float se[2][CH][16];
    __shared__ __align__(16) float sa[2][CH][16];

    int b = blockIdx.x >> 2, dq = blockIdx.x & 3;
    int tid = threadIdx.x;
    int dl = tid >> 3, h = tid & 7;
    int d = dq * 16 + dl;
    int sbase = h * 8;

    for (int q = tid; q < 2 * CH * 14; q += 128) {
        int bf = q / (CH * 14), rem = q % (CH * 14), t = rem / 14, p = rem % 14;
        sw[bf][t][50 + p] = 0.f;
    }

    u64 mv2[4];
#pragma unroll
    for (int i = 0; i < 4; ++i) {
        int s0 = sbase + 2 * i, s1 = s0 + 1;
        float lo = (s0 < SS) ? Mv0[s0 * DD + d] : 0.f;
        float hi = (s1 < SS) ? Mv0[s1 * DD + d] : 0.f;
        mv2[i] = pack2(lo, hi);
    }

    const float* gw = g_w + (size_t)b * TT * SS;
    const float* ge = g_e + (size_t)b * TT * DD + dq * 16;
    const float* ga = g_a + (size_t)b * TT * DD + dq * 16;
    float* gr = g_r + (size_t)b * TT * DD + dq * 16;

    float2 wreg[4];
    float4 eareg, areg;
    bool do_e = tid < 80;
    bool do_a2 = tid >= 48;
    int et = tid >> 2, ep = tid & 3;
    int at = (tid - 48) >> 2, ap = (tid - 48) & 3;

#pragma unroll
    for (int n = 0; n < 4; n++) {
        int q = tid + 128 * n;
        if (q < CH * 25) { int t = q / 25, p = q % 25; wreg[n] = *(const float2*)(gw + (size_t)t * SS + 2 * p); }
    }
    if (do_e)  eareg = *(const float4*)(ge + (size_t)et * DD + 4 * ep);
    if (do_a2) areg  = *(const float4*)(ga + (size_t)at * DD + 4 * ap);

#pragma unroll
    for (int n = 0; n < 4; n++) {
        int q = tid + 128 * n;
        if (q < CH * 25) { int t = q / 25, p = q % 25; *(float2*)&sw[0][t][2 * p] = wreg[n]; }
    }
    if (do_e)  *(float4*)&se[0][et][4 * ep] = eareg;
    if (do_a2) *(float4*)&sa[0][at][4 * ap] = areg;
    __syncthreads();

    for (int c = 0; c < TT / CH; ++c) {
        int cur = c & 1;
        if (c < TT / CH - 1) {
            int t0 = (c + 1) * CH;
#pragma unroll
            for (int n = 0; n < 4; n++) {
                int q = tid + 128 * n;
                if (q < CH * 25) { int t = q / 25, p = q % 25; wreg[n] = *(const float2*)(gw + (size_t)(t0 + t) * SS + 2 * p); }
            }
            if (do_e)  eareg = *(const float4*)(ge + (size_t)(t0 + et) * DD + 4 * ep);
            if (do_a2) areg  = *(const float4*)(ga + (size_t)(t0 + at) * DD + 4 * ap);
        }

        int t0 = c * CH;
#pragma unroll
        for (int tl = 0; tl < CH; ++tl) {
            float e_d = se[cur][tl][dl];
            float a_d = sa[cur][tl][dl];
            u64 ne2 = splat2(-e_d);
            u64 as2 = splat2(a_d);
            ulonglong2 wA = *(const ulonglong2*)&sw[cur][tl][sbase];
            ulonglong2 wB = *(const ulonglong2*)&sw[cur][tl][sbase + 4];
            u64 r2a = ffma2(wA.x, mv2[0], 0ull);
            u64 r2b = ffma2(wA.y, mv2[1], 0ull);
            r2a = ffma2(wB.x, mv2[2], r2a);
            r2b = ffma2(wB.y, mv2[3], r2b);
            mv2[0] = ffma2(wA.x, ffma2(mv2[0], ne2, as2), mv2[0]);
            mv2[1] = ffma2(wA.y, ffma2(mv2[1], ne2, as2), mv2[1]);
            mv2[2] = ffma2(wB.x, ffma2(mv2[2], ne2, as2), mv2[2]);
            mv2[3] = ffma2(wB.y, ffma2(mv2[3], ne2, as2), mv2[3]);
            float2 rr = unpack2(fadd2(r2a, r2b));
            float r = rr.x + rr.y;
            r += __shfl_xor_sync(0xffffffffu, r, 1);
            r += __shfl_xor_sync(0xffffffffu, r, 2);
            r += __shfl_xor_sync(0xffffffffu, r, 4);
            if (h == 0) gr[(size_t)(t0 + tl) * DD + dl] = r;
        }

        if (c < TT / CH - 1) {
            int nb = cur ^ 1;
#pragma unroll
            for (int n = 0; n < 4; n++) {
                int q = tid + 128 * n;
                if (q < CH * 25) { int t = q / 25, p = q % 25; *(float2*)&sw[nb][t][2 * p] = wreg[n]; }
            }
            if (do_e)  *(float4*)&se[nb][et][4 * ep] = eareg;
            if (do_a2) *(float4*)&sa[nb][at][4 * ap] = areg;
        }
        __syncthreads();
    }
}

// ============================================================
// k_out: grid 250, 2 tiles of 64 tokens. (R11/R15-best — unchanged)
// ============================================================
__global__ __launch_bounds__(256) void k_out(const int* __restrict__ concept,
                                             const float* __restrict__ ek,
                                             const float* __restrict__ Wf,
                                             const float* __restrict__ bf,
                                             const float* __restrict__ Wab,
                                             const float* __restrict__ bab,
                                             const float* __restrict__ Wd,
                                             const float* __restrict__ bd,
                                             float* __restrict__ out) {
    float* sWf = dynsh;
    float* sx  = dynsh + 8192;
    __shared__ int sc_[64];

    int tid = threadIdx.x;
    int td = tid & 15, tt = tid >> 4;

    float4* sWf4w = (float4*)sWf;
    const float4* Wf4 = (const float4*)Wf;
    for (int q = tid; q < 2048; q += 256) sWf4w[q] = Wf4[q];

    float4 bfv = *(const float4*)(bf + 4 * td);
    float4 wabv = *(const float4*)(Wab + 4 * td);
    float4 wdv = *(const float4*)(Wd + 4 * td);
    float bab0 = bab[0], bd0 = bd[0];

    for (int tile = 0; tile < 2; ++tile) {
        int base = (blockIdx.x * 2 + tile) * 64;

        __syncthreads();
        if (tid < 64) sc_[tid] = concept[base + tid];
        __syncthreads();

        float4* sx4 = (float4*)sx;
        const float4* gr4 = (const float4*)g_r;
        const float4* ek4 = (const float4*)ek;
        for (int q = tid; q < 1024; q += 256) {
            int tok = q >> 4, kk = q & 15;
            sx4[tok * 32 + kk] = gr4[(size_t)(base + tok) * 16 + kk];
            sx4[tok * 32 + 16 + kk] = ek4[(size_t)sc_[tok] * 16 + kk];
        }
        __syncthreads();

        const float4* sWf4 = (const float4*)sWf;
        u64 acc[4][2];
#pragma unroll
        for (int j = 0; j < 4; ++j) { acc[j][0] = 0ull; acc[j][1] = 0ull; }

#pragma unroll
        for (int kk = 0; kk < 32; ++kk) {
            ulonglong2 w0 = *(const ulonglong2*)(sWf4 + (4 * kk + 0) * 16 + td);
            ulonglong2 w1 = *(const ulonglong2*)(sWf4 + (4 * kk + 1) * 16 + td);
            ulonglong2 w2 = *(const ulonglong2*)(sWf4 + (4 * kk + 2) * 16 + td);
            ulonglong2 w3 = *(const ulonglong2*)(sWf4 + (4 * kk + 3) * 16 + td);
#pragma unroll
            for (int j = 0; j < 4; ++j) {
                float4 xv = sx4[(tt + 16 * j) * 32 + kk];
                u64 x0 = splat2(xv.x), x1 = splat2(xv.y), x2 = splat2(xv.z), x3 = splat2(xv.w);
                acc[j][0] = ffma2(x0, w0.x, acc[j][0]);
                acc[j][1] = ffma2(x0, w0.y, acc[j][1]);
                acc[j][0] = ffma2(x1, w1.x, acc[j][0]);
                acc[j][1] = ffma2(x1, w1.y, acc[j][1]);
                acc[j][0] = ffma2(x2, w2.x, acc[j][0]);
                acc[j][1] = ffma2(x2, w2.y, acc[j][1]);
                acc[j][0] = ffma2(x3, w3.x, acc[j][0]);
                acc[j][1] = ffma2(x3, w3.y, acc[j][1]);
            }
        }

#pragma unroll
        for (int j = 0; j < 4; ++j) {
            int tok = tt + 16 * j;
            float2 a01 = unpack2(acc[j][0]);
            float2 a23 = unpack2(acc[j][1]);
            float f0 = fast_tanh(a01.x + bfv.x);
            float f1 = fast_tanh(a01.y + bfv.y);
            float f2 = fast_tanh(a23.x + bfv.z);
            float f3 = fast_tanh(a23.y + bfv.w);
            float pa = f0 * wabv.x + f1 * wabv.y + f2 * wabv.z + f3 * wabv.w;
            float4 kd = *(const float4*)&sx[tok * 128 + 64 + 4 * td];
            float pq = kd.x * wdv.x + kd.y * wdv.y + kd.z * wdv.z + kd.w * wdv.w;
#pragma unroll
            for (int o = 8; o > 0; o >>= 1) {
                pa += __shfl_xor_sync(0xffffffffu, pa, o);
                pq += __shfl_xor_sync(0xffffffffu, pq, o);
            }
            if (td == 0) {
                float val = 3.f * fast_tanh(pa + bab0) - fast_tanh(pq + bd0);
                out[base + tok] = fast_sigmoid(val);
            }
        }
    }
}

// ============================================================
extern "C" void kernel_launch(void* const* d_in, const int* in_sizes, int n_in,
                              void* d_out, int out_size) {
    const int*   concept = (const int*)d_in[0];
    const int*   correct = (const int*)d_in[1];
    const int*   nc      = (const int*)d_in[2];
    const float* ek      = (const float*)d_in[3];
    const float* ev      = (const float*)d_in[4];
    const float* Mk      = (const float*)d_in[5];
    const float* Mv0     = (const float*)d_in[6];
    const float* Wf      = (const float*)d_in[7];
    const float* bf      = (const float*)d_in[8];
    const float* We      = (const float*)d_in[9];
    const float* be      = (const float*)d_in[10];
    const float* Wa      = (const float*)d_in[11];
    const float* ba      = (const float*)d_in[12];
    const float* Wab     = (const float*)d_in[13];
    const float* bab     = (const float*)d_in[14];
    const float* Wd      = (const float*)d_in[15];
    const float* bd      = (const float*)d_in[16];
    float* out = (float*)d_out;

    const int FRONT_SMEM = 19760 * sizeof(float);   // ~77KB
    const int OUT_SMEM   = 16384 * sizeof(float);   // 64KB
    cudaFuncSetAttribute(k_front, cudaFuncAttributeMaxDynamicSharedMemorySize, FRONT_SMEM);
    cudaFuncSetAttribute(k_out,   cudaFuncAttributeMaxDynamicSharedMemorySize, OUT_SMEM);

    k_front<<<250, 256, FRONT_SMEM>>>(concept, correct, nc, ek, ev, Mk, We, be, Wa, ba);
    k_scan<<<256, 128>>>(Mv0);
    k_out<<<250, 256, OUT_SMEM>>>(concept, ek, Wf, bf, Wab, bab, Wd, bd, out);
}

// round 17
// speedup vs baseline: 1.7409x; 1.1876x over previous
#include <cuda_runtime.h>
#include <math.h>

#define BB 64
#define TT 500
#define SS 50
#define DD 64
#define NTOK (BB*TT)
#define NC 1024
#define NX 2048

typedef unsigned long long u64;

__device__ float g_r[(size_t)NTOK*DD];
__device__ float g_wlut[(size_t)NC*52];
__device__ float g_elut[(size_t)NX*64];
__device__ float g_alut[(size_t)NX*64];
__device__ float g_kplut[(size_t)NC*64];
__device__ float g_qdlut[NC];

__device__ __forceinline__ float fast_sigmoid(float x) {
    return 1.f / (1.f + __expf(-x));
}
__device__ __forceinline__ float fast_tanh(float x) {
    return fmaf(2.f, fast_sigmoid(2.f * x), -1.f);
}

// ---- packed f32x2 helpers ----
__device__ __forceinline__ u64 ffma2(u64 a, u64 b, u64 c) {
    u64 d;
    asm("fma.rn.f32x2 %0, %1, %2, %3;" : "=l"(d) : "l"(a), "l"(b), "l"(c));
    return d;
}
__device__ __forceinline__ u64 fadd2(u64 a, u64 b) {
    u64 d;
    asm("add.rn.f32x2 %0, %1, %2;" : "=l"(d) : "l"(a), "l"(b));
    return d;
}
__device__ __forceinline__ u64 splat2(float x) {
    u64 d;
    asm("mov.b64 %0, {%1, %1};" : "=l"(d) : "r"(__float_as_uint(x)));
    return d;
}
__device__ __forceinline__ u64 pack2(float lo, float hi) {
    u64 d;
    asm("mov.b64 %0, {%1, %2};" : "=l"(d) : "r"(__float_as_uint(lo)), "r"(__float_as_uint(hi)));
    return d;
}
__device__ __forceinline__ float2 unpack2(u64 v) {
    unsigned int lo, hi;
    asm("mov.b64 {%0, %1}, %2;" : "=r"(lo), "=r"(hi) : "l"(v));
    return make_float2(__uint_as_float(lo), __uint_as_float(hi));
}

extern __shared__ float dynsh[];

// ============================================================
// k_lut_ea: e/a gates for all 2048 distinct x rows.
// Grid 64, 256 thr, 32 rows/block. td=tid&15 (4 dims), tt=tid>>4,
// rows tt+16j, j=0..1.
// ============================================================
__global__ __launch_bounds__(256) void k_lut_ea(const float* __restrict__ ev,
                                                const float* __restrict__ We,
                                                const float* __restrict__ be,
                                                const float* __restrict__ Wa,
                                                const float* __restrict__ ba) {
    __shared__ __align__(16) float sWe[4096];
    __shared__ __align__(16) float sWa[4096];
    __shared__ __align__(16) float sxv[2048];

    int tid = threadIdx.x;
    int td = tid & 15, tt = tid >> 4;
    int base = blockIdx.x * 32;

    {
        float4* a4 = (float4*)sWe;
        float4* b4 = (float4*)sWa;
        const float4* We4 = (const float4*)We;
        const float4* Wa4 = (const float4*)Wa;
        for (int q = tid; q < 1024; q += 256) {
            a4[q] = We4[q];
            b4[q] = Wa4[q];
        }
    }
    {
        float4* x4 = (float4*)sxv;
        const float4* ev4 = (const float4*)ev;
        for (int q = tid; q < 512; q += 256) {
            int tok = q >> 4, kk = q & 15;
            x4[q] = ev4[(size_t)(base + tok) * 16 + kk];
        }
    }
    __syncthreads();

    const float4* sWe4 = (const float4*)sWe;
    const float4* sWa4 = (const float4*)sWa;
    const float4* sx4 = (const float4*)sxv;
    u64 ae[2][2], aa[2][2];
#pragma unroll
    for (int j = 0; j < 2; ++j) {
        ae[j][0] = ae[j][1] = 0ull;
        aa[j][0] = aa[j][1] = 0ull;
    }

#pragma unroll
    for (int kk = 0; kk < 16; ++kk) {
        ulonglong2 e0 = *(const ulonglong2*)(sWe4 + (4 * kk + 0) * 16 + td);
        ulonglong2 e1 = *(const ulonglong2*)(sWe4 + (4 * kk + 1) * 16 + td);
        ulonglong2 e2 = *(const ulonglong2*)(sWe4 + (4 * kk + 2) * 16 + td);
        ulonglong2 e3 = *(const ulonglong2*)(sWe4 + (4 * kk + 3) * 16 + td);
        ulonglong2 a0 = *(const ulonglong2*)(sWa4 + (4 * kk + 0) * 16 + td);
        ulonglong2 a1 = *(const ulonglong2*)(sWa4 + (4 * kk + 1) * 16 + td);
        ulonglong2 a2 = *(const ulonglong2*)(sWa4 + (4 * kk + 2) * 16 + td);
        ulonglong2 a3 = *(const ulonglong2*)(sWa4 + (4 * kk + 3) * 16 + td);
#pragma unroll
        for (int j = 0; j < 2; ++j) {
            float4 xv = sx4[(tt + 16 * j) * 16 + kk];
            u64 x0 = splat2(xv.x), x1 = splat2(xv.y), x2 = splat2(xv.z), x3 = splat2(xv.w);
            ae[j][0] = ffma2(x0, e0.x, ae[j][0]);
            ae[j][1] = ffma2(x0, e0.y, ae[j][1]);
            aa[j][0] = ffma2(x0, a0.x, aa[j][0]);
            aa[j][1] = ffma2(x0, a0.y, aa[j][1]);
            ae[j][0] = ffma2(x1, e1.x, ae[j][0]);
            ae[j][1] = ffma2(x1, e1.y, ae[j][1]);
            aa[j][0] = ffma2(x1, a1.x, aa[j][0]);
            aa[j][1] = ffma2(x1, a1.y, aa[j][1]);
            ae[j][0] = ffma2(x2, e2.x, ae[j][0]);
            ae[j][1] = ffma2(x2, e2.y, ae[j][1]);
            aa[j][0] = ffma2(x2, a2.x, aa[j][0]);
            aa[j][1] = ffma2(x2, a2.y, aa[j][1]);
            ae[j][0] = ffma2(x3, e3.x, ae[j][0]);
            ae[j][1] = ffma2(x3, e3.y, ae[j][1]);
            aa[j][0] = ffma2(x3, a3.x, aa[j][0]);
            aa[j][1] = ffma2(x3, a3.y, aa[j][1]);
        }
    }

    float4 bev = *(const float4*)(be + 4 * td);
    float4 bav = *(const float4*)(ba + 4 * td);
#pragma unroll
    for (int j = 0; j < 2; ++j) {
        size_t row = (size_t)(base + tt + 16 * j);
        float2 ae01 = unpack2(ae[j][0]);
        float2 ae23 = unpack2(ae[j][1]);
        float2 aa01 = unpack2(aa[j][0]);
        float2 aa23 = unpack2(aa[j][1]);
        float4 eo, ao;
        eo.x = fast_sigmoid(ae01.x + bev.x);
        eo.y = fast_sigmoid(ae01.y + bev.y);
        eo.z = fast_sigmoid(ae23.x + bev.z);
        eo.w = fast_sigmoid(ae23.y + bev.w);
        ao.x = fast_tanh(aa01.x + bav.x);
        ao.y = fast_tanh(aa01.y + bav.y);
        ao.z = fast_tanh(aa23.x + bav.z);
        ao.w = fast_tanh(aa23.y + bav.w);
        *(float4*)(g_elut + row * 64 + 4 * td) = eo;
        *(float4*)(g_alut + row * 64 + 4 * td) = ao;
    }
}

// ============================================================
// k_lut_w: per-concept softmax w_lut, kpart_lut = k@Wf_k, qd_lut.
// Grid 32, 256 thr, 32 c-rows/block.
// ============================================================
__global__ __launch_bounds__(256) void k_lut_w(const float* __restrict__ ek,
                                               const float* __restrict__ Mk,
                                               const float* __restrict__ Wf,
                                               const float* __restrict__ Wd,
                                               const float* __restrict__ bd) {
    __shared__ __align__(16) float sMkT[3376];
    __shared__ __align__(16) float sWfk[4096];
    __shared__ __align__(16) float sxk[2048];
    __shared__ float sWd_[64];

    int tid = threadIdx.x;
    int td = tid & 15, tt = tid >> 4;
    int base = blockIdx.x * 32;

    for (int q = tid; q < 3376; q += 256) sMkT[q] = 0.f;
    if (tid < 64) sWd_[tid] = Wd[tid];
    __syncthreads();
    for (int q = tid; q < SS * DD; q += 256) {
        int s = q >> 6, k = q & 63;
        sMkT[k * 52 + s] = Mk[q];
    }
    {
        float4* f4 = (float4*)sWfk;
        const float4* Wf4 = (const float4*)Wf;
        for (int q = tid; q < 1024; q += 256) f4[q] = Wf4[1024 + q];
        float4* x4 = (float4*)sxk;
        const float4* ek4 = (const float4*)ek;
        for (int q = tid; q < 512; q += 256) {
            int tok = q >> 4, kk = q & 15;
            x4[q] = ek4[(size_t)(base + tok) * 16 + kk];
        }
    }
    __syncthreads();

    const float4* sM4 = (const float4*)sMkT;   // row stride 13 f4
    const float4* sF4 = (const float4*)sWfk;
    const float4* sx4 = (const float4*)sxk;
    u64 acc[2][2], ap[2][2];
#pragma unroll
    for (int j = 0; j < 2; ++j) {
        acc[j][0] = acc[j][1] = 0ull;
        ap[j][0] = ap[j][1] = 0ull;
    }

#pragma unroll
    for (int kk = 0; kk < 16; ++kk) {
        ulonglong2 m0 = *(const ulonglong2*)(sM4 + (4 * kk + 0) * 13 + td);
        ulonglong2 m1 = *(const ulonglong2*)(sM4 + (4 * kk + 1) * 13 + td);
        ulonglong2 m2 = *(const ulonglong2*)(sM4 + (4 * kk + 2) * 13 + td);
        ulonglong2 m3 = *(const ulonglong2*)(sM4 + (4 * kk + 3) * 13 + td);
        ulonglong2 f0 = *(const ulonglong2*)(sF4 + (4 * kk + 0) * 16 + td);
        ulonglong2 f1 = *(const ulonglong2*)(sF4 + (4 * kk + 1) * 16 + td);
        ulonglong2 f2 = *(const ulonglong2*)(sF4 + (4 * kk + 2) * 16 + td);
        ulonglong2 f3 = *(const ulonglong2*)(sF4 + (4 * kk + 3) * 16 + td);
#pragma unroll
        for (int j = 0; j < 2; ++j) {
            float4 xk = sx4[(tt + 16 * j) * 16 + kk];
            u64 k0 = splat2(xk.x), k1 = splat2(xk.y), k2 = splat2(xk.z), k3 = splat2(xk.w);
            acc[j][0] = ffma2(k0, m0.x, acc[j][0]);
            acc[j][1] = ffma2(k0, m0.y, acc[j][1]);
            ap[j][0]  = ffma2(k0, f0.x, ap[j][0]);
            ap[j][1]  = ffma2(k0, f0.y, ap[j][1]);
            acc[j][0] = ffma2(k1, m1.x, acc[j][0]);
            acc[j][1] = ffma2(k1, m1.y, acc[j][1]);
            ap[j][0]  = ffma2(k1, f1.x, ap[j][0]);
            ap[j][1]  = ffma2(k1, f1.y, ap[j][1]);
            acc[j][0] = ffma2(k2, m2.x, acc[j][0]);
            acc[j][1] = ffma2(k2, m2.y, acc[j][1]);
            ap[j][0]  = ffma2(k2, f2.x, ap[j][0]);
            ap[j][1]  = ffma2(k2, f2.y, ap[j][1]);
            acc[j][0] = ffma2(k3, m3.x, acc[j][0]);
            acc[j][1] = ffma2(k3, m3.y, acc[j][1]);
            ap[j][0]  = ffma2(k3, f3.x, ap[j][0]);
            ap[j][1]  = ffma2(k3, f3.y, ap[j][1]);
        }
    }

    // softmax + kpart epilogues
#pragma unroll
    for (int j = 0; j < 2; ++j) {
        int row = base + tt + 16 * j;
        float2 a01 = unpack2(acc[j][0]);
        float2 a23 = unpack2(acc[j][1]);
        float s0 = (4 * td + 0) < SS ? __expf(a01.x) : 0.f;
        float s1 = (4 * td + 1) < SS ? __expf(a01.y) : 0.f;
        float s2 = (4 * td + 2) < SS ? __expf(a23.x) : 0.f;
        float s3 = (4 * td + 3) < SS ? __expf(a23.y) : 0.f;
        float p = s0 + s1 + s2 + s3;
        p += __shfl_xor_sync(0xffffffffu, p, 1);
        p += __shfl_xor_sync(0xffffffffu, p, 2);
        p += __shfl_xor_sync(0xffffffffu, p, 4);
        p += __shfl_xor_sync(0xffffffffu, p, 8);
        float inv = 1.f / p;
        float* gwp = g_wlut + (size_t)row * 52 + 4 * td;
        if (td < 12) {
            *(float2*)gwp       = make_float2(s0 * inv, s1 * inv);
            *(float2*)(gwp + 2) = make_float2(s2 * inv, s3 * inv);
        } else if (td == 12) {
            *(float2*)gwp       = make_float2(s0 * inv, s1 * inv);
        }
        float2 p01 = unpack2(ap[j][0]);
        float2 p23 = unpack2(ap[j][1]);
        *(float4*)(g_kplut + (size_t)row * 64 + 4 * td) =
            make_float4(p01.x, p01.y, p23.x, p23.y);
    }

    // qd: 8 warps x 4 rows each
    {
        float bd0 = bd[0];
        int wd = tid >> 5, lane = tid & 31;
#pragma unroll
        for (int rr = 0; rr < 4; ++rr) {
            int row = wd * 4 + rr;
            float v = sxk[row * 64 + lane] * sWd_[lane]
                    + sxk[row * 64 + 32 + lane] * sWd_[32 + lane];
#pragma unroll
            for (int o = 16; o > 0; o >>= 1)
                v += __shfl_xor_sync(0xffffffffu, v, o);
            if (lane == 0) g_qdlut[base + row] = fast_tanh(v + bd0);
        }
    }
}

// ============================================================
// k_scan: R15-best structure; staging gathers from LUTs via indices.
// 256 blocks = (b, dq), 128 thr, CH=20, 1 barrier/chunk.
// ============================================================
#define CH 20
__global__ __launch_bounds__(128) void k_scan(const float* __restrict__ Mv0,
                                              const int* __restrict__ concept,
                                              const int* __restrict__ correct,
                                              const int* __restrict__ nc_ptr) {
    __shared__ __align__(16) float sw[2][CH][64];
    __shared__ __align__(16) float se[2][CH][16];
    __shared__ __align__(16) float sa[2][CH][16];

    int b = blockIdx.x >> 2, dq = blockIdx.x & 3;
    int tid = threadIdx.x;
    int dl = tid >> 3, h = tid & 7;
    int d = dq * 16 + dl;
    int sbase = h * 8;
    int nc = *nc_ptr;

    for (int q = tid; q < 2 * CH * 14; q += 128) {
        int bf = q / (CH * 14), rem = q % (CH * 14), t = rem / 14, p = rem % 14;
        sw[bf][t][50 + p] = 0.f;
    }

    u64 mv2[4];
#pragma unroll
    for (int i = 0; i < 4; ++i) {
        int s0 = sbase + 2 * i, s1 = s0 + 1;
        float lo = (s0 < SS) ? Mv0[s0 * DD + d] : 0.f;
        float hi = (s1 < SS) ? Mv0[s1 * DD + d] : 0.f;
        mv2[i] = pack2(lo, hi);
    }

    const int* cseq = concept + (size_t)b * TT;
    const int* rseq = correct + (size_t)b * TT;
    float* gr = g_r + (size_t)b * TT * DD + dq * 16;

    float2 wreg[4];
    float4 eareg, areg;
    bool do_e = tid < 80;
    bool do_a2 = tid >= 48;
    int et = tid >> 2, ep = tid & 3;
    int at = (tid - 48) >> 2, ap = (tid - 48) & 3;

    // initial chunk
#pragma unroll
    for (int n = 0; n < 4; n++) {
        int q = tid + 128 * n;
        if (q < CH * 25) {
            int t = q / 25, p = q % 25;
            int c_ = __ldg(cseq + t);
            wreg[n] = *(const float2*)(g_wlut + (size_t)c_ * 52 + 2 * p);
        }
    }
    if (do_e) {
        int x = __ldg(cseq + et) + nc * __ldg(rseq + et);
        eareg = *(const float4*)(g_elut + (size_t)x * 64 + dq * 16 + 4 * ep);
    }
    if (do_a2) {
        int x = __ldg(cseq + at) + nc * __ldg(rseq + at);
        areg = *(const float4*)(g_alut + (size_t)x * 64 + dq * 16 + 4 * ap);
    }

#pragma unroll
    for (int n = 0; n < 4; n++) {
        int q = tid + 128 * n;
        if (q < CH * 25) { int t = q / 25, p = q % 25; *(float2*)&sw[0][t][2 * p] = wreg[n]; }
    }
    if (do_e)  *(float4*)&se[0][et][4 * ep] = eareg;
    if (do_a2) *(float4*)&sa[0][at][4 * ap] = areg;
    __syncthreads();

    for (int c = 0; c < TT / CH; ++c) {
        int cur = c & 1;
        if (c < TT / CH - 1) {
            int t0n = (c + 1) * CH;
#pragma unroll
            for (int n = 0; n < 4; n++) {
                int q = tid + 128 * n;
                if (q < CH * 25) {
                    int t = q / 25, p = q % 25;
                    int c_ = __ldg(cseq + t0n + t);
                    wreg[n] = *(const float2*)(g_wlut + (size_t)c_ * 52 + 2 * p);
                }
            }
            if (do_e) {
                int x = __ldg(cseq + t0n + et) + nc * __ldg(rseq + t0n + et);
                eareg = *(const float4*)(g_elut + (size_t)x * 64 + dq * 16 + 4 * ep);
            }
            if (do_a2) {
                int x = __ldg(cseq + t0n + at) + nc * __ldg(rseq + t0n + at);
                areg = *(const float4*)(g_alut + (size_t)x * 64 + dq * 16 + 4 * ap);
            }
        }

        int t0 = c * CH;
#pragma unroll
        for (int tl = 0; tl < CH; ++tl) {
            float e_d = se[cur][tl][dl];
            float a_d = sa[cur][tl][dl];
            u64 ne2 = splat2(-e_d);
            u64 as2 = splat2(a_d);
            ulonglong2 wA = *(const ulonglong2*)&sw[cur][tl][sbase];
            ulonglong2 wB = *(const ulonglong2*)&sw[cur][tl][sbase + 4];
            u64 r2a = ffma2(wA.x, mv2[0], 0ull);
            u64 r2b = ffma2(wA.y, mv2[1], 0ull);
            r2a = ffma2(wB.x, mv2[2], r2a);
            r2b = ffma2(wB.y, mv2[3], r2b);
            mv2[0] = ffma2(wA.x, ffma2(mv2[0], ne2, as2), mv2[0]);
            mv2[1] = ffma2(wA.y, ffma2(mv2[1], ne2, as2), mv2[1]);
            mv2[2] = ffma2(wB.x, ffma2(mv2[2], ne2, as2), mv2[2]);
            mv2[3] = ffma2(wB.y, ffma2(mv2[3], ne2, as2), mv2[3]);
            float2 rr = unpack2(fadd2(r2a, r2b));
            float r = rr.x + rr.y;
            r += __shfl_xor_sync(0xffffffffu, r, 1);
            r += __shfl_xor_sync(0xffffffffu, r, 2);
            r += __shfl_xor_sync(0xffffffffu, r, 4);
            if (h == 0) gr[(size_t)(t0 + tl) * DD + dl] = r;
        }

        if (c < TT / CH - 1) {
            int nb = cur ^ 1;
#pragma unroll
            for (int n = 0; n < 4; n++) {
                int q = tid + 128 * n;
                if (q < CH * 25) { int t = q / 25, p = q % 25; *(float2*)&sw[nb][t][2 * p] = wreg[n]; }
            }
            if (do_e)  *(float4*)&se[nb][et][4 * ep] = eareg;
            if (do_a2) *(float4*)&sa[nb][at][4 * ap] = areg;
        }
        __syncthreads();
    }
}

// ============================================================
// k_out: halved matvec (r-part only) + kpart/qd LUTs.
// Grid 250, 2 tiles of 64 tokens, Wf_r staged once. 48KB dyn smem.
// ============================================================
__global__ __launch_bounds__(256) void k_out(const int* __restrict__ concept,
                                             const float* __restrict__ Wf,
                                             const float* __restrict__ bf,
                                             const float* __restrict__ Wab,
                                             const float* __restrict__ bab,
                                             float* __restrict__ out) {
    float* sWf = dynsh;                 // 4096 floats (Wf rows 0..63)
    float* sx  = dynsh + 4096;          // 8192 floats: 64 tok x (r[64]|kpart[64])
    __shared__ int sc_[64];

    int tid = threadIdx.x;
    int td = tid & 15, tt = tid >> 4;

    {
        float4* w4 = (float4*)sWf;
        const float4* Wf4 = (const float4*)Wf;
        for (int q = tid; q < 1024; q += 256) w4[q] = Wf4[q];
    }

    float4 bfv = *(const float4*)(bf + 4 * td);
    float4 wabv = *(const float4*)(Wab + 4 * td);
    float bab0 = bab[0];

    for (int tile = 0; tile < 2; ++tile) {
        int base = (blockIdx.x * 2 + tile) * 64;

        __syncthreads();
        if (tid < 64) sc_[tid] = concept[base + tid];
        __syncthreads();

        float4* sx4 = (float4*)sx;
        const float4* gr4 = (const float4*)g_r;
        const float4* kp4 = (const float4*)g_kplut;
        for (int q = tid; q < 1024; q += 256) {
            int tok = q >> 4, kk = q & 15;
            sx4[tok * 32 + kk] = gr4[(size_t)(base + tok) * 16 + kk];
            sx4[tok * 32 + 16 + kk] = kp4[(size_t)sc_[tok] * 16 + kk];
        }
        __syncthreads();

        const float4* sWf4 = (const float4*)sWf;
        u64 acc[4][2];
#pragma unroll
        for (int j = 0; j < 4; ++j) { acc[j][0] = 0ull; acc[j][1] = 0ull; }

#pragma unroll
        for (int kk = 0; kk < 16; ++kk) {
            ulonglong2 w0 = *(const ulonglong2*)(sWf4 + (4 * kk + 0) * 16 + td);
            ulonglong2 w1 = *(const ulonglong2*)(sWf4 + (4 * kk + 1) * 16 + td);
            ulonglong2 w2 = *(const ulonglong2*)(sWf4 + (4 * kk + 2) * 16 + td);
            ulonglong2 w3 = *(const ulonglong2*)(sWf4 + (4 * kk + 3) * 16 + td);
#pragma unroll
            for (int j = 0; j < 4; ++j) {
                float4 xv = sx4[(tt + 16 * j) * 32 + kk];
                u64 x0 = splat2(xv.x), x1 = splat2(xv.y), x2 = splat2(xv.z), x3 = splat2(xv.w);
                acc[j][0] = ffma2(x0, w0.x, acc[j][0]);
                acc[j][1] = ffma2(x0, w0.y, acc[j][1]);
                acc[j][0] = ffma2(x1, w1.x, acc[j][0]);
                acc[j][1] = ffma2(x1, w1.y, acc[j][1]);
                acc[j][0] = ffma2(x2, w2.x, acc[j][0]);
                acc[j][1] = ffma2(x2, w2.y, acc[j][1]);
                acc[j][0] = ffma2(x3, w3.x, acc[j][0]);
                acc[j][1] = ffma2(x3, w3.y, acc[j][1]);
            }
        }

#pragma unroll
        for (int j = 0; j < 4; ++j) {
            int tok = tt + 16 * j;
            float2 a01 = unpack2(acc[j][0]);
            float2 a23 = unpack2(acc[j][1]);
            float4 kp = *(const float4*)&sx[tok * 128 + 64 + 4 * td];
            float f0 = fast_tanh(a01.x + kp.x + bfv.x);
            float f1 = fast_tanh(a01.y + kp.y + bfv.y);
            float f2 = fast_tanh(a23.x + kp.z + bfv.z);
            float f3 = fast_tanh(a23.y + kp.w + bfv.w);
            float pa = f0 * wabv.x + f1 * wabv.y + f2 * wabv.z + f3 * wabv.w;
#pragma unroll
            for (int o = 8; o > 0; o >>= 1)
                pa += __shfl_xor_sync(0xffffffffu, pa, o);
            if (td == 0) {
                float qd = g_qdlut[sc_[tok]];
                float val = 3.f * fast_tanh(pa + bab0) - qd;
                out[base + tok] = fast_sigmoid(val);
            }
        }
    }
}

// ============================================================
extern "C" void kernel_launch(void* const* d_in, const int* in_sizes, int n_in,
                              void* d_out, int out_size) {
    const int*   concept = (const int*)d_in[0];
    const int*   correct = (const int*)d_in[1];
    const int*   nc      = (const int*)d_in[2];
    const float* ek      = (const float*)d_in[3];
    const float* ev      = (const float*)d_in[4];
    const float* Mk      = (const float*)d_in[5];
    const float* Mv0     = (const float*)d_in[6];
    const float* Wf      = (const float*)d_in[7];
    const float* bf      = (const float*)d_in[8];
    const float* We      = (const float*)d_in[9];
    const float* be      = (const float*)d_in[10];
    const float* Wa      = (const float*)d_in[11];
    const float* ba      = (const float*)d_in[12];
    const float* Wab     = (const float*)d_in[13];
    const float* bab     = (const float*)d_in[14];
    const float* Wd      = (const float*)d_in[15];
    const float* bd      = (const float*)d_in[16];
    float* out = (float*)d_out;

    const int OUT_SMEM = 12288 * sizeof(float);   // 48KB
    cudaFuncSetAttribute(k_out, cudaFuncAttributeMaxDynamicSharedMemorySize, OUT_SMEM);

    k_lut_ea<<<64, 256>>>(ev, We, be, Wa, ba);
    k_lut_w<<<32, 256>>>(ek, Mk, Wf, Wd, bd);
    k_scan<<<256, 128>>>(Mv0, concept, correct, nc);
    k_out<<<250, 256, OUT_SMEM>>>(concept, Wf, bf, Wab, bab, out);
}